// round 5
// baseline (speedup 1.0000x reference)
#include <cuda_runtime.h>
#include <cuda_bf16.h>
#include <math.h>
#include <stdint.h>

#define NB   2
#define C    288
#define M    9
#define D    32
#define H    64
#define W    64
#define P    4096
#define HKV  32
#define WKV  32
#define S    1024
#define FEAT 144

// ---------------- device scratch ----------------
__device__ float g_wt [4 * C * C];          // transposed weights
__device__ float g_xkv[NB * C * S];
__device__ float g_qt [NB * P * C];         // [n][p][o]
__device__ float g_kt [NB * S * C];         // [n][s][o]
__device__ float g_vt [NB * S * C];         // [n][s][o]
__device__ float g_khi[NB * S * C];
__device__ float g_klo[NB * S * C];
__device__ float g_vhi[NB * S * C];
__device__ float g_vlo[NB * S * C];
__device__ float g_pfx[M * W * D * WKV];    // [m][i][d][j]
__device__ float g_pfy[M * H * D * HKV];
__device__ float g_ctx[NB * C];
__device__ float g_mix[NB * M];
__device__ float g_ex [NB * M * P * 32];    // [n][m][p][v]
__device__ float g_ey [NB * M * P * 32];    // [n][m][p][u]
__device__ float g_attn[(size_t)NB * P * S];
__device__ float g_aot[NB * C * P];         // attn output transposed [n][o][p]

// ---------------- tf32 helpers ----------------
__device__ __forceinline__ void split_tf32(float v, uint32_t& hi, uint32_t& lo) {
    asm("cvt.rna.tf32.f32 %0, %1;" : "=r"(hi) : "f"(v));
    float l = v - __uint_as_float(hi);
    asm("cvt.rna.tf32.f32 %0, %1;" : "=r"(lo) : "f"(l));
}
__device__ __forceinline__ void mma_tf32(float* c, const uint32_t* a, const uint32_t* b) {
    asm volatile(
        "mma.sync.aligned.m16n8k8.row.col.f32.tf32.tf32.f32 "
        "{%0,%1,%2,%3}, {%4,%5,%6,%7}, {%8,%9}, {%0,%1,%2,%3};"
        : "+f"(c[0]), "+f"(c[1]), "+f"(c[2]), "+f"(c[3])
        : "r"(a[0]), "r"(a[1]), "r"(a[2]), "r"(a[3]), "r"(b[0]), "r"(b[1]));
}

// ---------------- small kernels ----------------
__global__ void transpose_kernel(const float* __restrict__ Wq, const float* __restrict__ Wk,
                                 const float* __restrict__ Wv, const float* __restrict__ Wp,
                                 float* __restrict__ wt) {
    __shared__ float tile[32][33];
    const float* src = (blockIdx.z == 0) ? Wq : (blockIdx.z == 1) ? Wk
                     : (blockIdx.z == 2) ? Wv : Wp;
    float* dst = wt + (size_t)blockIdx.z * C * C;
    int r0 = blockIdx.y * 32, c0 = blockIdx.x * 32;
    int tx = threadIdx.x, ty = threadIdx.y;
    for (int i = ty; i < 32; i += 8) tile[i][tx] = src[(size_t)(r0 + i) * C + c0 + tx];
    __syncthreads();
    for (int i = ty; i < 32; i += 8) dst[(size_t)(c0 + i) * C + r0 + tx] = tile[tx][i];
}

__global__ void xkv_kernel(const float* __restrict__ x, float* __restrict__ xkv) {
    int idx = blockIdx.x * 256 + threadIdx.x;
    if (idx >= NB * C * S) return;
    int s = idx & (S - 1);
    int c = (idx >> 10) % C;
    int n = idx / (C * S);
    int u = s >> 5, v = s & 31;
    xkv[idx] = x[((size_t)n * C + c) * P + u * 128 + v * 2];
}

__global__ void split_kv_kernel(const float* __restrict__ kt, const float* __restrict__ vt,
                                float* __restrict__ khi, float* __restrict__ klo,
                                float* __restrict__ vhi, float* __restrict__ vlo) {
    int idx = blockIdx.x * 256 + threadIdx.x;
    if (idx >= NB * S * C) return;
    uint32_t hi, lo;
    split_tf32(kt[idx], hi, lo);
    khi[idx] = __uint_as_float(hi);
    klo[idx] = __uint_as_float(lo);
    split_tf32(vt[idx], hi, lo);
    vhi[idx] = __uint_as_float(hi);
    vlo[idx] = __uint_as_float(lo);
}

// out[n][p][o] = sum_c X[n][c][p] * WT[c][o]
__global__ __launch_bounds__(384)
void proj_kernel(const float* __restrict__ X, const float* __restrict__ WT,
                 float* __restrict__ out, int Pn) {
    __shared__ float Xs[32 * 64];
    __shared__ float Ws[32 * 96];
    int n = blockIdx.z;
    const float* Xn = X + (size_t)n * C * Pn;
    float* outn = out + (size_t)n * Pn * C;
    int p0 = blockIdx.x * 64, o0 = blockIdx.y * 96;
    int t = threadIdx.x;
    int pi = t & 15, oj = t >> 4;
    float acc[4][4] = {};
    for (int c0 = 0; c0 < C; c0 += 32) {
        for (int i = t; i < 2048; i += 384)
            Xs[i] = Xn[(size_t)(c0 + (i >> 6)) * Pn + p0 + (i & 63)];
        for (int i = t; i < 3072; i += 384)
            Ws[i] = WT[(size_t)(c0 + i / 96) * C + o0 + i % 96];
        __syncthreads();
        #pragma unroll
        for (int kk = 0; kk < 32; kk++) {
            float4 xv = *(const float4*)&Xs[kk * 64 + pi * 4];
            float4 wv = *(const float4*)&Ws[kk * 96 + oj * 4];
            acc[0][0] += xv.x * wv.x; acc[0][1] += xv.x * wv.y;
            acc[0][2] += xv.x * wv.z; acc[0][3] += xv.x * wv.w;
            acc[1][0] += xv.y * wv.x; acc[1][1] += xv.y * wv.y;
            acc[1][2] += xv.y * wv.z; acc[1][3] += xv.y * wv.w;
            acc[2][0] += xv.z * wv.x; acc[2][1] += xv.z * wv.y;
            acc[2][2] += xv.z * wv.z; acc[2][3] += xv.z * wv.w;
            acc[3][0] += xv.w * wv.x; acc[3][1] += xv.w * wv.y;
            acc[3][2] += xv.w * wv.z; acc[3][3] += xv.w * wv.w;
        }
        __syncthreads();
    }
    #pragma unroll
    for (int r = 0; r < 4; r++) {
        float4 v = make_float4(acc[r][0], acc[r][1], acc[r][2], acc[r][3]);
        *(float4*)&outn[(size_t)(p0 + pi * 4 + r) * C + o0 + oj * 4] = v;
    }
}

// K and V projections in one launch (z = n*2 + which)
__global__ __launch_bounds__(384)
void kvproj_kernel(const float* __restrict__ X, const float* __restrict__ wt,
                   float* __restrict__ kt, float* __restrict__ vt) {
    __shared__ float Xs[32 * 64];
    __shared__ float Ws[32 * 96];
    int n = blockIdx.z >> 1, which = blockIdx.z & 1;
    const float* Xn = X + (size_t)n * C * S;
    const float* WT = wt + (size_t)(1 + which) * C * C;
    float* outn = (which ? vt : kt) + (size_t)n * S * C;
    int p0 = blockIdx.x * 64, o0 = blockIdx.y * 96;
    int t = threadIdx.x;
    int pi = t & 15, oj = t >> 4;
    float acc[4][4] = {};
    for (int c0 = 0; c0 < C; c0 += 32) {
        for (int i = t; i < 2048; i += 384)
            Xs[i] = Xn[(size_t)(c0 + (i >> 6)) * S + p0 + (i & 63)];
        for (int i = t; i < 3072; i += 384)
            Ws[i] = WT[(size_t)(c0 + i / 96) * C + o0 + i % 96];
        __syncthreads();
        #pragma unroll
        for (int kk = 0; kk < 32; kk++) {
            float4 xv = *(const float4*)&Xs[kk * 64 + pi * 4];
            float4 wv = *(const float4*)&Ws[kk * 96 + oj * 4];
            acc[0][0] += xv.x * wv.x; acc[0][1] += xv.x * wv.y;
            acc[0][2] += xv.x * wv.z; acc[0][3] += xv.x * wv.w;
            acc[1][0] += xv.y * wv.x; acc[1][1] += xv.y * wv.y;
            acc[1][2] += xv.y * wv.z; acc[1][3] += xv.y * wv.w;
            acc[2][0] += xv.z * wv.x; acc[2][1] += xv.z * wv.y;
            acc[2][2] += xv.z * wv.z; acc[2][3] += xv.z * wv.w;
            acc[3][0] += xv.w * wv.x; acc[3][1] += xv.w * wv.y;
            acc[3][2] += xv.w * wv.z; acc[3][3] += xv.w * wv.w;
        }
        __syncthreads();
    }
    #pragma unroll
    for (int r = 0; r < 4; r++) {
        float4 v = make_float4(acc[r][0], acc[r][1], acc[r][2], acc[r][3]);
        *(float4*)&outn[(size_t)(p0 + pi * 4 + r) * C + o0 + oj * 4] = v;
    }
}

__global__ void context_kernel(const float* __restrict__ qt, float* __restrict__ ctx) {
    int o0 = blockIdx.x * 32, n = blockIdx.y;
    int lane = threadIdx.x & 31, w = threadIdx.x >> 5;
    const float* q = qt + (size_t)n * P * C + o0 + lane;
    float s = 0.f;
    for (int p = w; p < P; p += 8) s += q[(size_t)p * C];
    __shared__ float red[8][32];
    red[w][lane] = s;
    __syncthreads();
    if (w == 0) {
        float tot = 0.f;
        #pragma unroll
        for (int i = 0; i < 8; i++) tot += red[i][lane];
        ctx[n * C + o0 + lane] = tot * (1.0f / (float)P);
    }
}

__global__ void mix_kernel(const float* __restrict__ ctx, const float* __restrict__ Wc,
                           const float* __restrict__ bc, float* __restrict__ mixw) {
    int n = blockIdx.x;
    __shared__ float lg[M];
    int m = threadIdx.x;
    if (m < M) {
        float s = bc[m];
        const float* cn = ctx + n * C;
        const float* wm = Wc + m * C;
        for (int o = 0; o < C; o++) s += cn[o] * wm[o];
        lg[m] = s;
    }
    __syncthreads();
    if (m == 0) {
        float mx = lg[0];
        #pragma unroll
        for (int i = 1; i < M; i++) mx = fmaxf(mx, lg[i]);
        float e[M], sum = 0.f;
        #pragma unroll
        for (int i = 0; i < M; i++) { e[i] = expf(lg[i] - mx); sum += e[i]; }
        #pragma unroll
        for (int i = 0; i < M; i++) mixw[n * M + i] = e[i] / sum;
    }
}

__global__ void pos_kernel(const float* __restrict__ Wx, const float* __restrict__ Wy,
                           float* __restrict__ pfx, float* __restrict__ pfy) {
    __shared__ float emb[FEAT];
    int j = blockIdx.x, i = blockIdx.y;
    int t = threadIdx.x;
    float diff = (float)i - 2.0f * (float)j;
    if (t < FEAT) {
        int l = (t < 72) ? t : (t - 72);
        float dm = powf(1000.0f, (4.0f / 288.0f) * (float)l);
        float wd = diff / dm;
        emb[t] = (t < 72) ? sinf(wd) : cosf(wd);
    }
    __syncthreads();
    float sx = 0.f, sy = 0.f;
    const float* wxr = Wx + t * FEAT;
    const float* wyr = Wy + t * FEAT;
    #pragma unroll 4
    for (int l = 0; l < FEAT; l++) {
        float e = emb[l];
        sx += e * wxr[l];
        sy += e * wyr[l];
    }
    const float inv_sqrt2 = 0.70710678118654752f;
    int m = t >> 5, dd = t & 31;
    int idx = ((m * 64 + i) * 32 + dd) * 32 + j;
    pfx[idx] = sx * inv_sqrt2;
    pfy[idx] = sy * inv_sqrt2;
}

__global__ __launch_bounds__(256)
void ex_kernel(const float* __restrict__ qt, const float* __restrict__ pfx,
               float* __restrict__ ex) {
    __shared__ float qs[64 * 33];
    __shared__ float pfs[32 * 33];
    int w = blockIdx.x, m = blockIdx.y, n = blockIdx.z;
    int t = threadIdx.x;
    for (int i = t; i < 1024; i += 256)
        pfs[(i >> 5) * 33 + (i & 31)] = pfx[(m * 64 + w) * 1024 + i];
    for (int i = t; i < 2048; i += 256) {
        int hh = i >> 5, dd = i & 31;
        qs[hh * 33 + dd] = qt[((size_t)n * P + hh * 64 + w) * C + m * 32 + dd];
    }
    __syncthreads();
    int v = t & 31, h0 = t >> 5;
    #pragma unroll
    for (int r = 0; r < 8; r++) {
        int h = h0 + 8 * r;
        float a = 0.f;
        #pragma unroll
        for (int dd = 0; dd < 32; dd++)
            a += qs[h * 33 + dd] * pfs[dd * 33 + v];
        ex[((size_t)(n * M + m) * P + h * 64 + w) * 32 + v] = a;
    }
}

__global__ __launch_bounds__(256)
void ey_kernel(const float* __restrict__ qt, const float* __restrict__ pfy,
               float* __restrict__ ey) {
    __shared__ float qs[64 * 33];
    __shared__ float pfs[32 * 33];
    int h = blockIdx.x, m = blockIdx.y, n = blockIdx.z;
    int t = threadIdx.x;
    for (int i = t; i < 1024; i += 256)
        pfs[(i >> 5) * 33 + (i & 31)] = pfy[(m * 64 + h) * 1024 + i];
    for (int i = t; i < 2048; i += 256) {
        int ww = i >> 5, dd = i & 31;
        qs[ww * 33 + dd] = qt[((size_t)n * P + h * 64 + ww) * C + m * 32 + dd];
    }
    __syncthreads();
    int u = t & 31, w0 = t >> 5;
    #pragma unroll
    for (int r = 0; r < 8; r++) {
        int ww = w0 + 8 * r;
        float a = 0.f;
        #pragma unroll
        for (int dd = 0; dd < 32; dd++)
            a += qs[ww * 33 + dd] * pfs[dd * 33 + u];
        ey[((size_t)(n * M + m) * P + h * 64 + ww) * 32 + u] = a;
    }
}

// ---------------- fused energy + softmax + head-mix ----------------
// Block: 32 query rows, all S, all M heads. attn[n][p][s] = sum_m w_m softmax(e_m)
// smem floats: E 32*1025 | QH/QL 32*36 | KH/KL 128*36 | EXs/EYs 1024 | red 256 | smax/ssum 32
#define FA_E    (32 * 1025)
#define FA_Q    (32 * 36)
#define FA_K    (128 * 36)
#define FA_SMEM (FA_E + 2*FA_Q + 2*FA_K + 2*1024 + 256 + 64)

__global__ __launch_bounds__(256, 1)
void fused_attn_kernel(const float* __restrict__ qt, const float* __restrict__ khi,
                       const float* __restrict__ klo, const float* __restrict__ ex,
                       const float* __restrict__ ey, const float* __restrict__ mixw,
                       float* __restrict__ attn) {
    extern __shared__ float sm[];
    float* E    = sm;
    float* QH   = E + FA_E;
    float* QL   = QH + FA_Q;
    float* KH   = QL + FA_Q;
    float* KL   = KH + FA_K;
    float* EXs  = KL + FA_K;
    float* EYs  = EXs + 1024;
    float* red  = EYs + 1024;
    float* smax = red + 256;
    float* ssum = smax + 32;

    int t = threadIdx.x;
    int p0 = blockIdx.x * 32;
    int n = blockIdx.y;
    int warp = t >> 5, lane = t & 31, g = lane >> 2, tg = lane & 3;

    const float* qn = qt + (size_t)n * P * C;
    float acc[128];
    #pragma unroll
    for (int j = 0; j < 128; j++) acc[j] = 0.f;

    for (int m = 0; m < M; m++) {
        // q tile + pos tiles
        for (int i = t; i < 1024; i += 256) {
            int pl = i >> 5, dd = i & 31;
            uint32_t hi, lo;
            split_tf32(qn[(size_t)(p0 + pl) * C + m * 32 + dd], hi, lo);
            QH[pl * 36 + dd] = __uint_as_float(hi);
            QL[pl * 36 + dd] = __uint_as_float(lo);
        }
        size_t exbase = ((size_t)(n * M + m) * P + p0) * 32;
        for (int i = t; i < 1024; i += 256) { EXs[i] = ex[exbase + i]; EYs[i] = ey[exbase + i]; }

        for (int ch = 0; ch < 8; ch++) {
            int s0 = ch * 128;
            for (int i = t; i < 4096; i += 256) {
                int sl = i >> 5, dd = i & 31;
                size_t gi = ((size_t)n * S + s0 + sl) * C + m * 32 + dd;
                KH[sl * 36 + dd] = khi[gi];
                KL[sl * 36 + dd] = klo[gi];
            }
            __syncthreads();
            float eacc[2][2][4] = {};
            #pragma unroll
            for (int ki = 0; ki < 4; ki++) {
                uint32_t ah[2][4], al[2][4];
                #pragma unroll
                for (int mt = 0; mt < 2; mt++) {
                    int pb = mt * 16;
                    ah[mt][0] = __float_as_uint(QH[(pb + g) * 36 + ki * 8 + tg]);
                    ah[mt][1] = __float_as_uint(QH[(pb + g + 8) * 36 + ki * 8 + tg]);
                    ah[mt][2] = __float_as_uint(QH[(pb + g) * 36 + ki * 8 + tg + 4]);
                    ah[mt][3] = __float_as_uint(QH[(pb + g + 8) * 36 + ki * 8 + tg + 4]);
                    al[mt][0] = __float_as_uint(QL[(pb + g) * 36 + ki * 8 + tg]);
                    al[mt][1] = __float_as_uint(QL[(pb + g + 8) * 36 + ki * 8 + tg]);
                    al[mt][2] = __float_as_uint(QL[(pb + g) * 36 + ki * 8 + tg + 4]);
                    al[mt][3] = __float_as_uint(QL[(pb + g + 8) * 36 + ki * 8 + tg + 4]);
                }
                #pragma unroll
                for (int nf = 0; nf < 2; nf++) {
                    int sb = warp * 16 + nf * 8;
                    uint32_t bh[2], bl[2];
                    bh[0] = __float_as_uint(KH[(sb + g) * 36 + ki * 8 + tg]);
                    bh[1] = __float_as_uint(KH[(sb + g) * 36 + ki * 8 + tg + 4]);
                    bl[0] = __float_as_uint(KL[(sb + g) * 36 + ki * 8 + tg]);
                    bl[1] = __float_as_uint(KL[(sb + g) * 36 + ki * 8 + tg + 4]);
                    #pragma unroll
                    for (int mt = 0; mt < 2; mt++) {
                        mma_tf32(eacc[mt][nf], ah[mt], bh);
                        mma_tf32(eacc[mt][nf], ah[mt], bl);
                        mma_tf32(eacc[mt][nf], al[mt], bh);
                    }
                }
            }
            // epilogue: add pos bias, write to E
            #pragma unroll
            for (int mt = 0; mt < 2; mt++) {
                #pragma unroll
                for (int nf = 0; nf < 2; nf++) {
                    int sgl = s0 + warp * 16 + nf * 8 + tg * 2;
                    int u = sgl >> 5, v0 = sgl & 31, v1 = (sgl + 1) & 31;
                    #pragma unroll
                    for (int half = 0; half < 2; half++) {
                        int pl = mt * 16 + g + half * 8;
                        E[pl * 1025 + sgl]     = eacc[mt][nf][half * 2]
                                                 + EXs[pl * 32 + v0] + EYs[pl * 32 + u];
                        E[pl * 1025 + sgl + 1] = eacc[mt][nf][half * 2 + 1]
                                                 + EXs[pl * 32 + v1] + EYs[pl * 32 + u];
                    }
                }
            }
            __syncthreads();
        }

        // ---- softmax over s per row, accumulate mix-weighted ----
        // phase A: row maxima
        #pragma unroll
        for (int r = 0; r < 32; r++) {
            float lm = -1e30f;
            #pragma unroll
            for (int q = 0; q < 4; q++) lm = fmaxf(lm, E[r * 1025 + t + 256 * q]);
            #pragma unroll
            for (int off = 16; off > 0; off >>= 1)
                lm = fmaxf(lm, __shfl_xor_sync(0xffffffffu, lm, off));
            if (lane == 0) red[r * 8 + warp] = lm;
        }
        __syncthreads();
        if (t < 32) {
            float v = red[t * 8];
            #pragma unroll
            for (int i = 1; i < 8; i++) v = fmaxf(v, red[t * 8 + i]);
            smax[t] = v;
        }
        __syncthreads();
        // phase C: exp in-place + row sums
        #pragma unroll
        for (int r = 0; r < 32; r++) {
            float mx = smax[r];
            float ls = 0.f;
            #pragma unroll
            for (int q = 0; q < 4; q++) {
                int a = r * 1025 + t + 256 * q;
                float v = __expf(E[a] - mx);
                E[a] = v;
                ls += v;
            }
            #pragma unroll
            for (int off = 16; off > 0; off >>= 1)
                ls += __shfl_xor_sync(0xffffffffu, ls, off);
            if (lane == 0) red[r * 8 + warp] = ls;
        }
        __syncthreads();
        if (t < 32) {
            float v = 0.f;
            #pragma unroll
            for (int i = 0; i < 8; i++) v += red[t * 8 + i];
            ssum[t] = v;
        }
        __syncthreads();
        // phase D: weighted accumulate
        float wm = mixw[n * M + m];
        #pragma unroll
        for (int r = 0; r < 32; r++) {
            float sc = wm / ssum[r];
            #pragma unroll
            for (int q = 0; q < 4; q++)
                acc[r * 4 + q] += sc * E[r * 1025 + t + 256 * q];
        }
        __syncthreads();
    }

    float* ap = attn + ((size_t)n * P + p0) * (size_t)S;
    #pragma unroll
    for (int r = 0; r < 32; r++)
        #pragma unroll
        for (int q = 0; q < 4; q++)
            ap[r * 1024 + 256 * q + t] = acc[r * 4 + q];
}

// ---------------- AV GEMM (tf32x3 mma, V pre-split) ----------------
__global__ __launch_bounds__(256)
void av_kernel(const float* __restrict__ attn, const float* __restrict__ vhi,
               const float* __restrict__ vlo, float* __restrict__ aot) {
    __shared__ float sm[11008];
    float* As_hi = sm;          // [64p][36]
    float* As_lo = sm + 2304;
    float* Bs_hi = sm + 4608;   // [32k][100]
    float* Bs_lo = sm + 7808;

    int o0 = blockIdx.x * 96, p0 = blockIdx.y * 64, n = blockIdx.z;
    int t = threadIdx.x;
    int warp = t >> 5, lane = t & 31;
    int g = lane >> 2, tg = lane & 3;
    int wp = warp & 1, wo = warp >> 1;

    const float* an = attn + (size_t)n * P * S;

    float acc[2][3][4];
    #pragma unroll
    for (int a = 0; a < 2; a++)
        #pragma unroll
        for (int b = 0; b < 3; b++)
            #pragma unroll
            for (int c = 0; c < 4; c++) acc[a][b][c] = 0.f;

    for (int k0 = 0; k0 < S; k0 += 32) {
        for (int i = t; i < 2048; i += 256) {
            int pl = i >> 5, kk = i & 31;
            uint32_t hi, lo;
            split_tf32(an[(size_t)(p0 + pl) * S + k0 + kk], hi, lo);
            As_hi[pl * 36 + kk] = __uint_as_float(hi);
            As_lo[pl * 36 + kk] = __uint_as_float(lo);
        }
        for (int i = t; i < 3072; i += 256) {
            int kk = i / 96, ol = i - kk * 96;
            size_t gi = ((size_t)n * S + k0 + kk) * C + o0 + ol;
            Bs_hi[kk * 100 + ol] = vhi[gi];
            Bs_lo[kk * 100 + ol] = vlo[gi];
        }
        __syncthreads();
        #pragma unroll
        for (int ks = 0; ks < 4; ks++) {
            uint32_t ah[2][4], al[2][4];
            #pragma unroll
            for (int mt = 0; mt < 2; mt++) {
                int pb = wp * 32 + mt * 16;
                ah[mt][0] = __float_as_uint(As_hi[(pb + g) * 36 + ks * 8 + tg]);
                ah[mt][1] = __float_as_uint(As_hi[(pb + g + 8) * 36 + ks * 8 + tg]);
                ah[mt][2] = __float_as_uint(As_hi[(pb + g) * 36 + ks * 8 + tg + 4]);
                ah[mt][3] = __float_as_uint(As_hi[(pb + g + 8) * 36 + ks * 8 + tg + 4]);
                al[mt][0] = __float_as_uint(As_lo[(pb + g) * 36 + ks * 8 + tg]);
                al[mt][1] = __float_as_uint(As_lo[(pb + g + 8) * 36 + ks * 8 + tg]);
                al[mt][2] = __float_as_uint(As_lo[(pb + g) * 36 + ks * 8 + tg + 4]);
                al[mt][3] = __float_as_uint(As_lo[(pb + g + 8) * 36 + ks * 8 + tg + 4]);
            }
            #pragma unroll
            for (int nf = 0; nf < 3; nf++) {
                int ob = wo * 24 + nf * 8;
                uint32_t bh[2], bl[2];
                bh[0] = __float_as_uint(Bs_hi[(ks * 8 + tg) * 100 + ob + g]);
                bh[1] = __float_as_uint(Bs_hi[(ks * 8 + tg + 4) * 100 + ob + g]);
                bl[0] = __float_as_uint(Bs_lo[(ks * 8 + tg) * 100 + ob + g]);
                bl[1] = __float_as_uint(Bs_lo[(ks * 8 + tg + 4) * 100 + ob + g]);
                #pragma unroll
                for (int mt = 0; mt < 2; mt++) {
                    mma_tf32(acc[mt][nf], ah[mt], bh);
                    mma_tf32(acc[mt][nf], ah[mt], bl);
                    mma_tf32(acc[mt][nf], al[mt], bh);
                }
            }
        }
        __syncthreads();
    }

    float* stage = sm;
    #pragma unroll
    for (int mt = 0; mt < 2; mt++)
        #pragma unroll
        for (int nf = 0; nf < 3; nf++)
            #pragma unroll
            for (int c = 0; c < 4; c++) {
                int oo = wo * 24 + nf * 8 + tg * 2 + (c & 1);
                int pp = wp * 32 + mt * 16 + g + ((c >> 1) * 8);
                stage[oo * 68 + pp] = acc[mt][nf][c];
            }
    __syncthreads();
    float* ab = aot + ((size_t)n * C + o0) * P + p0;
    for (int i = t; i < 96 * 64; i += 256) {
        int orr = i >> 6, pc = i & 63;
        ab[(size_t)orr * P + pc] = stage[orr * 68 + pc];
    }
}

// out[n][c][p] = gamma*(sum_o At[n][o][p]*WpT[o][c] + bp[c]) + x[n][c][p]
__global__ __launch_bounds__(384)
void final_kernel(const float* __restrict__ At, const float* __restrict__ WpT,
                  const float* __restrict__ bp, const float* __restrict__ x,
                  const float* __restrict__ gamma, float* __restrict__ out) {
    __shared__ float As[32 * 64];
    __shared__ float Ws[32 * 96];
    int n = blockIdx.z;
    const float* An = At + (size_t)n * C * P;
    int p0 = blockIdx.x * 64, c0 = blockIdx.y * 96;
    int t = threadIdx.x;
    int pi = t & 15, cj = t >> 4;
    float acc[4][4] = {};
    for (int o0 = 0; o0 < C; o0 += 32) {
        for (int i = t; i < 2048; i += 384)
            As[i] = An[(size_t)(o0 + (i >> 6)) * P + p0 + (i & 63)];
        for (int i = t; i < 3072; i += 384)
            Ws[i] = WpT[(size_t)(o0 + i / 96) * C + c0 + i % 96];
        __syncthreads();
        #pragma unroll
        for (int kk = 0; kk < 32; kk++) {
            float4 av = *(const float4*)&As[kk * 64 + pi * 4];
            float4 wv = *(const float4*)&Ws[kk * 96 + cj * 4];
            acc[0][0] += wv.x * av.x; acc[0][1] += wv.x * av.y;
            acc[0][2] += wv.x * av.z; acc[0][3] += wv.x * av.w;
            acc[1][0] += wv.y * av.x; acc[1][1] += wv.y * av.y;
            acc[1][2] += wv.y * av.z; acc[1][3] += wv.y * av.w;
            acc[2][0] += wv.z * av.x; acc[2][1] += wv.z * av.y;
            acc[2][2] += wv.z * av.z; acc[2][3] += wv.z * av.w;
            acc[3][0] += wv.w * av.x; acc[3][1] += wv.w * av.y;
            acc[3][2] += wv.w * av.z; acc[3][3] += wv.w * av.w;
        }
        __syncthreads();
    }
    float g = gamma[0];
    #pragma unroll
    for (int r = 0; r < 4; r++) {
        int c = c0 + cj * 4 + r;
        size_t base = ((size_t)n * C + c) * P + p0 + pi * 4;
        float4 xr = *(const float4*)&x[base];
        float b = bp[c];
        float4 v;
        v.x = g * (acc[r][0] + b) + xr.x;
        v.y = g * (acc[r][1] + b) + xr.y;
        v.z = g * (acc[r][2] + b) + xr.z;
        v.w = g * (acc[r][3] + b) + xr.w;
        *(float4*)&out[base] = v;
    }
}

// ---------------- launch ----------------
extern "C" void kernel_launch(void* const* d_in, const int* in_sizes, int n_in,
                              void* d_out, int out_size) {
    const float* x     = (const float*)d_in[0];
    const float* Wq    = (const float*)d_in[1];
    const float* Wk    = (const float*)d_in[2];
    const float* Wv    = (const float*)d_in[3];
    const float* Wx    = (const float*)d_in[4];
    const float* Wy    = (const float*)d_in[5];
    const float* Wproj = (const float*)d_in[6];
    const float* bproj = (const float*)d_in[7];
    const float* Wc    = (const float*)d_in[8];
    const float* bc    = (const float*)d_in[9];
    const float* gamma = (const float*)d_in[10];
    float* out = (float*)d_out;

    float *wt, *xkv, *qt, *kt, *vt, *khi, *klo, *vhi, *vlo;
    float *pfx, *pfy, *ctx, *mix, *exb, *eyb, *attn, *aot;
    cudaGetSymbolAddress((void**)&wt,  g_wt);
    cudaGetSymbolAddress((void**)&xkv, g_xkv);
    cudaGetSymbolAddress((void**)&qt,  g_qt);
    cudaGetSymbolAddress((void**)&kt,  g_kt);
    cudaGetSymbolAddress((void**)&vt,  g_vt);
    cudaGetSymbolAddress((void**)&khi, g_khi);
    cudaGetSymbolAddress((void**)&klo, g_klo);
    cudaGetSymbolAddress((void**)&vhi, g_vhi);
    cudaGetSymbolAddress((void**)&vlo, g_vlo);
    cudaGetSymbolAddress((void**)&pfx, g_pfx);
    cudaGetSymbolAddress((void**)&pfy, g_pfy);
    cudaGetSymbolAddress((void**)&ctx, g_ctx);
    cudaGetSymbolAddress((void**)&mix, g_mix);
    cudaGetSymbolAddress((void**)&exb, g_ex);
    cudaGetSymbolAddress((void**)&eyb, g_ey);
    cudaGetSymbolAddress((void**)&attn, g_attn);
    cudaGetSymbolAddress((void**)&aot, g_aot);

    size_t fa_smem = (size_t)FA_SMEM * sizeof(float);
    cudaFuncSetAttribute(fused_attn_kernel, cudaFuncAttributeMaxDynamicSharedMemorySize,
                         (int)fa_smem);

    transpose_kernel<<<dim3(9, 9, 4), dim3(32, 8)>>>(Wq, Wk, Wv, Wproj, wt);
    xkv_kernel<<<(NB * C * S + 255) / 256, 256>>>(x, xkv);
    proj_kernel<<<dim3(P / 64, 3, NB), 384>>>(x, wt + 0 * C * C, qt, P);
    kvproj_kernel<<<dim3(S / 64, 3, NB * 2), 384>>>(xkv, wt, kt, vt);
    split_kv_kernel<<<(NB * S * C + 255) / 256, 256>>>(kt, vt, khi, klo, vhi, vlo);
    context_kernel<<<dim3(C / 32, NB), 256>>>(qt, ctx);
    mix_kernel<<<NB, 32>>>(ctx, Wc, bc, mix);
    pos_kernel<<<dim3(WKV, W), 288>>>(Wx, Wy, pfx, pfy);
    ex_kernel<<<dim3(W, M, NB), 256>>>(qt, pfx, exb);
    ey_kernel<<<dim3(H, M, NB), 256>>>(qt, pfy, eyb);
    fused_attn_kernel<<<dim3(P / 32, NB), 256, fa_smem>>>(qt, khi, klo, exb, eyb, mix, attn);
    av_kernel<<<dim3(3, P / 64, NB), 256>>>(attn, vhi, vlo, aot);
    final_kernel<<<dim3(P / 64, 3, NB), 384>>>(aot, wt + 3 * C * C, bproj, x, gamma, out);
}

// round 7
// speedup vs baseline: 1.2150x; 1.2150x over previous
#include <cuda_runtime.h>
#include <cuda_bf16.h>
#include <math.h>
#include <stdint.h>

#define NB   2
#define C    288
#define M    9
#define D    32
#define H    64
#define W    64
#define P    4096
#define HKV  32
#define WKV  32
#define S    1024
#define FEAT 144

// ---------------- device scratch ----------------
__device__ float g_wt [4 * C * C];          // transposed weights
__device__ float g_xkv[NB * C * S];
__device__ float g_qt [NB * P * C];         // [n][p][o]
__device__ float g_khi[NB * S * C];
__device__ float g_klo[NB * S * C];
__device__ float g_vhi[NB * S * C];
__device__ float g_vlo[NB * S * C];
__device__ float g_pfx[M * W * D * WKV];    // [m][i][d][j]
__device__ float g_pfy[M * H * D * HKV];
__device__ float g_ctx[NB * C];
__device__ float g_mix[NB * M];
__device__ float g_ex [NB * M * P * 32];    // [n][m][p][v]
__device__ float g_ey [NB * M * P * 32];    // [n][m][p][u]
__device__ float g_attn[(size_t)NB * P * S];
__device__ float g_aot[NB * C * P];         // attn output transposed [n][o][p]

// ---------------- tf32 helpers ----------------
__device__ __forceinline__ void split_tf32(float v, uint32_t& hi, uint32_t& lo) {
    asm("cvt.rna.tf32.f32 %0, %1;" : "=r"(hi) : "f"(v));
    float l = v - __uint_as_float(hi);
    asm("cvt.rna.tf32.f32 %0, %1;" : "=r"(lo) : "f"(l));
}
__device__ __forceinline__ void mma_tf32(float* c, const uint32_t* a, const uint32_t* b) {
    asm volatile(
        "mma.sync.aligned.m16n8k8.row.col.f32.tf32.tf32.f32 "
        "{%0,%1,%2,%3}, {%4,%5,%6,%7}, {%8,%9}, {%0,%1,%2,%3};"
        : "+f"(c[0]), "+f"(c[1]), "+f"(c[2]), "+f"(c[3])
        : "r"(a[0]), "r"(a[1]), "r"(a[2]), "r"(a[3]), "r"(b[0]), "r"(b[1]));
}

// ---------------- small kernels ----------------
__global__ void transpose_kernel(const float* __restrict__ Wq, const float* __restrict__ Wk,
                                 const float* __restrict__ Wv, const float* __restrict__ Wp,
                                 float* __restrict__ wt) {
    __shared__ float tile[32][33];
    const float* src = (blockIdx.z == 0) ? Wq : (blockIdx.z == 1) ? Wk
                     : (blockIdx.z == 2) ? Wv : Wp;
    float* dst = wt + (size_t)blockIdx.z * C * C;
    int r0 = blockIdx.y * 32, c0 = blockIdx.x * 32;
    int tx = threadIdx.x, ty = threadIdx.y;
    for (int i = ty; i < 32; i += 8) tile[i][tx] = src[(size_t)(r0 + i) * C + c0 + tx];
    __syncthreads();
    for (int i = ty; i < 32; i += 8) dst[(size_t)(c0 + i) * C + r0 + tx] = tile[tx][i];
}

__global__ void xkv_kernel(const float* __restrict__ x, float* __restrict__ xkv) {
    int idx = blockIdx.x * 256 + threadIdx.x;
    if (idx >= NB * C * S) return;
    int s = idx & (S - 1);
    int c = (idx >> 10) % C;
    int n = idx / (C * S);
    int u = s >> 5, v = s & 31;
    xkv[idx] = x[((size_t)n * C + c) * P + u * 128 + v * 2];
}

// Q + K + V projections, one launch.  grid (96, 3, NB), block 384.
// bx<64: Q tile of x -> qt.  bx in [64,80): K tile of xkv -> khi/klo (tf32 split).
// bx in [80,96): V tile -> vhi/vlo.
__global__ __launch_bounds__(384)
void qkvproj_kernel(const float* __restrict__ x, const float* __restrict__ xkv,
                    const float* __restrict__ wt, float* __restrict__ qt,
                    float* __restrict__ khi, float* __restrict__ klo,
                    float* __restrict__ vhi, float* __restrict__ vlo) {
    __shared__ float Xs[32 * 64];
    __shared__ float Ws[32 * 96];
    int bx = blockIdx.x, n = blockIdx.z;
    int o0 = blockIdx.y * 96;
    const float* Xn;
    const float* WT;
    int Pn, p0, kind;
    if (bx < 64) {
        kind = 0; Xn = x + (size_t)n * C * P; Pn = P; p0 = bx * 64; WT = wt;
    } else {
        kind = 1 + ((bx - 64) >> 4);
        Xn = xkv + (size_t)n * C * S; Pn = S; p0 = ((bx - 64) & 15) * 64;
        WT = wt + (size_t)kind * C * C;
    }
    int t = threadIdx.x;
    int pi = t & 15, oj = t >> 4;
    float acc[4][4] = {};
    for (int c0 = 0; c0 < C; c0 += 32) {
        for (int i = t; i < 2048; i += 384)
            Xs[i] = Xn[(size_t)(c0 + (i >> 6)) * Pn + p0 + (i & 63)];
        for (int i = t; i < 3072; i += 384)
            Ws[i] = WT[(size_t)(c0 + i / 96) * C + o0 + i % 96];
        __syncthreads();
        #pragma unroll
        for (int kk = 0; kk < 32; kk++) {
            float4 xv = *(const float4*)&Xs[kk * 64 + pi * 4];
            float4 wv = *(const float4*)&Ws[kk * 96 + oj * 4];
            acc[0][0] += xv.x * wv.x; acc[0][1] += xv.x * wv.y;
            acc[0][2] += xv.x * wv.z; acc[0][3] += xv.x * wv.w;
            acc[1][0] += xv.y * wv.x; acc[1][1] += xv.y * wv.y;
            acc[1][2] += xv.y * wv.z; acc[1][3] += xv.y * wv.w;
            acc[2][0] += xv.z * wv.x; acc[2][1] += xv.z * wv.y;
            acc[2][2] += xv.z * wv.z; acc[2][3] += xv.z * wv.w;
            acc[3][0] += xv.w * wv.x; acc[3][1] += xv.w * wv.y;
            acc[3][2] += xv.w * wv.z; acc[3][3] += xv.w * wv.w;
        }
        __syncthreads();
    }
    if (kind == 0) {
        float* outn = qt + (size_t)n * P * C;
        #pragma unroll
        for (int r = 0; r < 4; r++) {
            float4 v = make_float4(acc[r][0], acc[r][1], acc[r][2], acc[r][3]);
            *(float4*)&outn[(size_t)(p0 + pi * 4 + r) * C + o0 + oj * 4] = v;
        }
    } else {
        float* ho = ((kind == 1) ? khi : vhi) + (size_t)n * S * C;
        float* lo = ((kind == 1) ? klo : vlo) + (size_t)n * S * C;
        #pragma unroll
        for (int r = 0; r < 4; r++) {
            uint32_t h[4], l[4];
            #pragma unroll
            for (int c = 0; c < 4; c++) split_tf32(acc[r][c], h[c], l[c]);
            float4 hv = make_float4(__uint_as_float(h[0]), __uint_as_float(h[1]),
                                    __uint_as_float(h[2]), __uint_as_float(h[3]));
            float4 lv = make_float4(__uint_as_float(l[0]), __uint_as_float(l[1]),
                                    __uint_as_float(l[2]), __uint_as_float(l[3]));
            size_t bi = (size_t)(p0 + pi * 4 + r) * C + o0 + oj * 4;
            *(float4*)&ho[bi] = hv;
            *(float4*)&lo[bi] = lv;
        }
    }
}

__global__ void context_kernel(const float* __restrict__ qt, float* __restrict__ ctx) {
    int o0 = blockIdx.x * 32, n = blockIdx.y;
    int lane = threadIdx.x & 31, w = threadIdx.x >> 5;
    const float* q = qt + (size_t)n * P * C + o0 + lane;
    float s = 0.f;
    for (int p = w; p < P; p += 8) s += q[(size_t)p * C];
    __shared__ float red[8][32];
    red[w][lane] = s;
    __syncthreads();
    if (w == 0) {
        float tot = 0.f;
        #pragma unroll
        for (int i = 0; i < 8; i++) tot += red[i][lane];
        ctx[n * C + o0 + lane] = tot * (1.0f / (float)P);
    }
}

__global__ void mix_kernel(const float* __restrict__ ctx, const float* __restrict__ Wc,
                           const float* __restrict__ bc, float* __restrict__ mixw) {
    int n = blockIdx.x;
    __shared__ float lg[M];
    int m = threadIdx.x;
    if (m < M) {
        float s = bc[m];
        const float* cn = ctx + n * C;
        const float* wm = Wc + m * C;
        for (int o = 0; o < C; o++) s += cn[o] * wm[o];
        lg[m] = s;
    }
    __syncthreads();
    if (m == 0) {
        float mx = lg[0];
        #pragma unroll
        for (int i = 1; i < M; i++) mx = fmaxf(mx, lg[i]);
        float e[M], sum = 0.f;
        #pragma unroll
        for (int i = 0; i < M; i++) { e[i] = expf(lg[i] - mx); sum += e[i]; }
        #pragma unroll
        for (int i = 0; i < M; i++) mixw[n * M + i] = e[i] / sum;
    }
}

__global__ void pos_kernel(const float* __restrict__ Wx, const float* __restrict__ Wy,
                           float* __restrict__ pfx, float* __restrict__ pfy) {
    __shared__ float emb[FEAT];
    int j = blockIdx.x, i = blockIdx.y;
    int t = threadIdx.x;
    float diff = (float)i - 2.0f * (float)j;
    if (t < FEAT) {
        int l = (t < 72) ? t : (t - 72);
        float dm = powf(1000.0f, (4.0f / 288.0f) * (float)l);
        float wd = diff / dm;
        emb[t] = (t < 72) ? sinf(wd) : cosf(wd);
    }
    __syncthreads();
    float sx = 0.f, sy = 0.f;
    const float* wxr = Wx + t * FEAT;
    const float* wyr = Wy + t * FEAT;
    #pragma unroll 4
    for (int l = 0; l < FEAT; l++) {
        float e = emb[l];
        sx += e * wxr[l];
        sy += e * wyr[l];
    }
    const float inv_sqrt2 = 0.70710678118654752f;
    int m = t >> 5, dd = t & 31;
    int idx = ((m * 64 + i) * 32 + dd) * 32 + j;
    pfx[idx] = sx * inv_sqrt2;
    pfy[idx] = sy * inv_sqrt2;
}

__global__ __launch_bounds__(256)
void ex_kernel(const float* __restrict__ qt, const float* __restrict__ pfx,
               float* __restrict__ ex) {
    __shared__ float qs[64 * 33];
    __shared__ float pfs[32 * 33];
    int w = blockIdx.x, m = blockIdx.y, n = blockIdx.z;
    int t = threadIdx.x;
    for (int i = t; i < 1024; i += 256)
        pfs[(i >> 5) * 33 + (i & 31)] = pfx[(m * 64 + w) * 1024 + i];
    for (int i = t; i < 2048; i += 256) {
        int hh = i >> 5, dd = i & 31;
        qs[hh * 33 + dd] = qt[((size_t)n * P + hh * 64 + w) * C + m * 32 + dd];
    }
    __syncthreads();
    int v = t & 31, h0 = t >> 5;
    #pragma unroll
    for (int r = 0; r < 8; r++) {
        int h = h0 + 8 * r;
        float a = 0.f;
        #pragma unroll
        for (int dd = 0; dd < 32; dd++)
            a += qs[h * 33 + dd] * pfs[dd * 33 + v];
        ex[((size_t)(n * M + m) * P + h * 64 + w) * 32 + v] = a;
    }
}

__global__ __launch_bounds__(256)
void ey_kernel(const float* __restrict__ qt, const float* __restrict__ pfy,
               float* __restrict__ ey) {
    __shared__ float qs[64 * 33];
    __shared__ float pfs[32 * 33];
    int h = blockIdx.x, m = blockIdx.y, n = blockIdx.z;
    int t = threadIdx.x;
    for (int i = t; i < 1024; i += 256)
        pfs[(i >> 5) * 33 + (i & 31)] = pfy[(m * 64 + h) * 1024 + i];
    for (int i = t; i < 2048; i += 256) {
        int ww = i >> 5, dd = i & 31;
        qs[ww * 33 + dd] = qt[((size_t)n * P + h * 64 + ww) * C + m * 32 + dd];
    }
    __syncthreads();
    int u = t & 31, w0 = t >> 5;
    #pragma unroll
    for (int r = 0; r < 8; r++) {
        int ww = w0 + 8 * r;
        float a = 0.f;
        #pragma unroll
        for (int dd = 0; dd < 32; dd++)
            a += qs[ww * 33 + dd] * pfs[dd * 33 + u];
        ey[((size_t)(n * M + m) * P + h * 64 + ww) * 32 + u] = a;
    }
}

// ---------------- fused energy + softmax + head-mix, v2 ----------------
// 512 threads, 32 query rows/block, K-chunks of 256, warp-per-row softmax.
// smem: E 32*1025 | QH/QL 32*36 | KH/KL 256*36 | EXs/EYs 1024
#define FA2_E   (32 * 1025)
#define FA2_Q   (32 * 36)
#define FA2_K   (256 * 36)
#define FA2_SMEM (FA2_E + 2 * FA2_Q + 2 * FA2_K + 2 * 1024)

__global__ __launch_bounds__(512, 1)
void fused_attn_kernel(const float* __restrict__ qt, const float* __restrict__ khi,
                       const float* __restrict__ klo, const float* __restrict__ ex,
                       const float* __restrict__ ey, const float* __restrict__ mixw,
                       float* __restrict__ attn) {
    extern __shared__ float sm[];
    float* E   = sm;
    float* QH  = E + FA2_E;
    float* QL  = QH + FA2_Q;
    float* KH  = QL + FA2_Q;
    float* KL  = KH + FA2_K;
    float* EXs = KL + FA2_K;
    float* EYs = EXs + 1024;

    int t = threadIdx.x;
    int p0 = blockIdx.x * 32;
    int n = blockIdx.y;
    int warp = t >> 5, lane = t & 31, g = lane >> 2, tg = lane & 3;
    int wp = warp & 1;          // row half (16 rows)
    int ws = warp >> 1;         // 0..7: 32-col segment within 256-col chunk

    const float* qn = qt + (size_t)n * P * C;
    float acc[2][32];
    #pragma unroll
    for (int a = 0; a < 2; a++)
        #pragma unroll
        for (int j = 0; j < 32; j++) acc[a][j] = 0.f;

    for (int m = 0; m < M; m++) {
        // Q tile (split) + pos tables
        for (int i = t; i < 1024; i += 512) {
            int pl = i >> 5, dd = i & 31;
            uint32_t hi, lo;
            split_tf32(qn[(size_t)(p0 + pl) * C + m * 32 + dd], hi, lo);
            QH[pl * 36 + dd] = __uint_as_float(hi);
            QL[pl * 36 + dd] = __uint_as_float(lo);
        }
        size_t exbase = ((size_t)(n * M + m) * P + p0) * 32;
        for (int i = t; i < 1024; i += 512) { EXs[i] = ex[exbase + i]; EYs[i] = ey[exbase + i]; }

        for (int ch = 0; ch < 4; ch++) {
            int s0 = ch * 256;
            for (int i = t; i < 8192; i += 512) {
                int sl = i >> 5, dd = i & 31;
                size_t gi = ((size_t)n * S + s0 + sl) * C + m * 32 + dd;
                KH[sl * 36 + dd] = khi[gi];
                KL[sl * 36 + dd] = klo[gi];
            }
            __syncthreads();
            float eacc[4][4] = {};
            #pragma unroll
            for (int ki = 0; ki < 4; ki++) {
                uint32_t ah[4], al[4];
                int pb = wp * 16;
                ah[0] = __float_as_uint(QH[(pb + g) * 36 + ki * 8 + tg]);
                ah[1] = __float_as_uint(QH[(pb + g + 8) * 36 + ki * 8 + tg]);
                ah[2] = __float_as_uint(QH[(pb + g) * 36 + ki * 8 + tg + 4]);
                ah[3] = __float_as_uint(QH[(pb + g + 8) * 36 + ki * 8 + tg + 4]);
                al[0] = __float_as_uint(QL[(pb + g) * 36 + ki * 8 + tg]);
                al[1] = __float_as_uint(QL[(pb + g + 8) * 36 + ki * 8 + tg]);
                al[2] = __float_as_uint(QL[(pb + g) * 36 + ki * 8 + tg + 4]);
                al[3] = __float_as_uint(QL[(pb + g + 8) * 36 + ki * 8 + tg + 4]);
                #pragma unroll
                for (int nf = 0; nf < 4; nf++) {
                    int sb = ws * 32 + nf * 8;
                    uint32_t bh[2], bl[2];
                    bh[0] = __float_as_uint(KH[(sb + g) * 36 + ki * 8 + tg]);
                    bh[1] = __float_as_uint(KH[(sb + g) * 36 + ki * 8 + tg + 4]);
                    bl[0] = __float_as_uint(KL[(sb + g) * 36 + ki * 8 + tg]);
                    bl[1] = __float_as_uint(KL[(sb + g) * 36 + ki * 8 + tg + 4]);
                    mma_tf32(eacc[nf], ah, bh);
                    mma_tf32(eacc[nf], ah, bl);
                    mma_tf32(eacc[nf], al, bh);
                }
            }
            // epilogue: add pos bias, write E
            #pragma unroll
            for (int nf = 0; nf < 4; nf++) {
                int sgl = s0 + ws * 32 + nf * 8 + tg * 2;
                int u = sgl >> 5, v0 = sgl & 31, v1 = (sgl + 1) & 31;
                #pragma unroll
                for (int half = 0; half < 2; half++) {
                    int pl = wp * 16 + g + half * 8;
                    E[pl * 1025 + sgl]     = eacc[nf][half * 2]
                                             + EXs[pl * 32 + v0] + EYs[pl * 32 + u];
                    E[pl * 1025 + sgl + 1] = eacc[nf][half * 2 + 1]
                                             + EXs[pl * 32 + v1] + EYs[pl * 32 + u];
                }
            }
            __syncthreads();
        }

        // ---- softmax: warp owns rows (warp, warp+16); pure intra-warp ----
        float wm = mixw[n * M + m];
        #pragma unroll
        for (int rr = 0; rr < 2; rr++) {
            float* Er = E + (warp + rr * 16) * 1025;
            float mx = -1e30f;
            #pragma unroll
            for (int j = 0; j < 32; j++) mx = fmaxf(mx, Er[lane + 32 * j]);
            #pragma unroll
            for (int off = 16; off > 0; off >>= 1)
                mx = fmaxf(mx, __shfl_xor_sync(0xffffffffu, mx, off));
            float ssum = 0.f;
            #pragma unroll
            for (int j = 0; j < 32; j++) {
                float v = __expf(Er[lane + 32 * j] - mx);
                Er[lane + 32 * j] = v;
                ssum += v;
            }
            #pragma unroll
            for (int off = 16; off > 0; off >>= 1)
                ssum += __shfl_xor_sync(0xffffffffu, ssum, off);
            float sc = wm / ssum;
            #pragma unroll
            for (int j = 0; j < 32; j++)
                acc[rr][j] += sc * Er[lane + 32 * j];
        }
        // no sync needed: next head's E writes are behind the chunk-load barrier
    }

    float* ap = attn + ((size_t)n * P + p0) * (size_t)S;
    #pragma unroll
    for (int rr = 0; rr < 2; rr++) {
        float* row = ap + (size_t)(warp + rr * 16) * S;
        #pragma unroll
        for (int j = 0; j < 32; j++)
            row[lane + 32 * j] = acc[rr][j];
    }
}

// ---------------- AV GEMM (tf32x3 mma, V pre-split) ----------------
__global__ __launch_bounds__(256)
void av_kernel(const float* __restrict__ attn, const float* __restrict__ vhi,
               const float* __restrict__ vlo, float* __restrict__ aot) {
    __shared__ float sm[11008];
    float* As_hi = sm;          // [64p][36]
    float* As_lo = sm + 2304;
    float* Bs_hi = sm + 4608;   // [32k][100]
    float* Bs_lo = sm + 7808;

    int o0 = blockIdx.x * 96, p0 = blockIdx.y * 64, n = blockIdx.z;
    int t = threadIdx.x;
    int warp = t >> 5, lane = t & 31;
    int g = lane >> 2, tg = lane & 3;
    int wp = warp & 1, wo = warp >> 1;

    const float* an = attn + (size_t)n * P * S;

    float acc[2][3][4];
    #pragma unroll
    for (int a = 0; a < 2; a++)
        #pragma unroll
        for (int b = 0; b < 3; b++)
            #pragma unroll
            for (int c = 0; c < 4; c++) acc[a][b][c] = 0.f;

    for (int k0 = 0; k0 < S; k0 += 32) {
        for (int i = t; i < 2048; i += 256) {
            int pl = i >> 5, kk = i & 31;
            uint32_t hi, lo;
            split_tf32(an[(size_t)(p0 + pl) * S + k0 + kk], hi, lo);
            As_hi[pl * 36 + kk] = __uint_as_float(hi);
            As_lo[pl * 36 + kk] = __uint_as_float(lo);
        }
        for (int i = t; i < 3072; i += 256) {
            int kk = i / 96, ol = i - kk * 96;
            size_t gi = ((size_t)n * S + k0 + kk) * C + o0 + ol;
            Bs_hi[kk * 100 + ol] = vhi[gi];
            Bs_lo[kk * 100 + ol] = vlo[gi];
        }
        __syncthreads();
        #pragma unroll
        for (int ks = 0; ks < 4; ks++) {
            uint32_t ah[2][4], al[2][4];
            #pragma unroll
            for (int mt = 0; mt < 2; mt++) {
                int pb = wp * 32 + mt * 16;
                ah[mt][0] = __float_as_uint(As_hi[(pb + g) * 36 + ks * 8 + tg]);
                ah[mt][1] = __float_as_uint(As_hi[(pb + g + 8) * 36 + ks * 8 + tg]);
                ah[mt][2] = __float_as_uint(As_hi[(pb + g) * 36 + ks * 8 + tg + 4]);
                ah[mt][3] = __float_as_uint(As_hi[(pb + g + 8) * 36 + ks * 8 + tg + 4]);
                al[mt][0] = __float_as_uint(As_lo[(pb + g) * 36 + ks * 8 + tg]);
                al[mt][1] = __float_as_uint(As_lo[(pb + g + 8) * 36 + ks * 8 + tg]);
                al[mt][2] = __float_as_uint(As_lo[(pb + g) * 36 + ks * 8 + tg + 4]);
                al[mt][3] = __float_as_uint(As_lo[(pb + g + 8) * 36 + ks * 8 + tg + 4]);
            }
            #pragma unroll
            for (int nf = 0; nf < 3; nf++) {
                int ob = wo * 24 + nf * 8;
                uint32_t bh[2], bl[2];
                bh[0] = __float_as_uint(Bs_hi[(ks * 8 + tg) * 100 + ob + g]);
                bh[1] = __float_as_uint(Bs_hi[(ks * 8 + tg + 4) * 100 + ob + g]);
                bl[0] = __float_as_uint(Bs_lo[(ks * 8 + tg) * 100 + ob + g]);
                bl[1] = __float_as_uint(Bs_lo[(ks * 8 + tg + 4) * 100 + ob + g]);
                #pragma unroll
                for (int mt = 0; mt < 2; mt++) {
                    mma_tf32(acc[mt][nf], ah[mt], bh);
                    mma_tf32(acc[mt][nf], ah[mt], bl);
                    mma_tf32(acc[mt][nf], al[mt], bh);
                }
            }
        }
        __syncthreads();
    }

    float* stage = sm;
    #pragma unroll
    for (int mt = 0; mt < 2; mt++)
        #pragma unroll
        for (int nf = 0; nf < 3; nf++)
            #pragma unroll
            for (int c = 0; c < 4; c++) {
                int oo = wo * 24 + nf * 8 + tg * 2 + (c & 1);
                int pp = wp * 32 + mt * 16 + g + ((c >> 1) * 8);
                stage[oo * 68 + pp] = acc[mt][nf][c];
            }
    __syncthreads();
    float* ab = aot + ((size_t)n * C + o0) * P + p0;
    for (int i = t; i < 96 * 64; i += 256) {
        int orr = i >> 6, pc = i & 63;
        ab[(size_t)orr * P + pc] = stage[orr * 68 + pc];
    }
}

// out[n][c][p] = gamma*(sum_o At[n][o][p]*WpT[o][c] + bp[c]) + x[n][c][p]
__global__ __launch_bounds__(384)
void final_kernel(const float* __restrict__ At, const float* __restrict__ WpT,
                  const float* __restrict__ bp, const float* __restrict__ x,
                  const float* __restrict__ gamma, float* __restrict__ out) {
    __shared__ float As[32 * 64];
    __shared__ float Ws[32 * 96];
    int n = blockIdx.z;
    const float* An = At + (size_t)n * C * P;
    int p0 = blockIdx.x * 64, c0 = blockIdx.y * 96;
    int t = threadIdx.x;
    int pi = t & 15, cj = t >> 4;
    float acc[4][4] = {};
    for (int o0 = 0; o0 < C; o0 += 32) {
        for (int i = t; i < 2048; i += 384)
            As[i] = An[(size_t)(o0 + (i >> 6)) * P + p0 + (i & 63)];
        for (int i = t; i < 3072; i += 384)
            Ws[i] = WpT[(size_t)(o0 + i / 96) * C + c0 + i % 96];
        __syncthreads();
        #pragma unroll
        for (int kk = 0; kk < 32; kk++) {
            float4 av = *(const float4*)&As[kk * 64 + pi * 4];
            float4 wv = *(const float4*)&Ws[kk * 96 + cj * 4];
            acc[0][0] += wv.x * av.x; acc[0][1] += wv.x * av.y;
            acc[0][2] += wv.x * av.z; acc[0][3] += wv.x * av.w;
            acc[1][0] += wv.y * av.x; acc[1][1] += wv.y * av.y;
            acc[1][2] += wv.y * av.z; acc[1][3] += wv.y * av.w;
            acc[2][0] += wv.z * av.x; acc[2][1] += wv.z * av.y;
            acc[2][2] += wv.z * av.z; acc[2][3] += wv.z * av.w;
            acc[3][0] += wv.w * av.x; acc[3][1] += wv.w * av.y;
            acc[3][2] += wv.w * av.z; acc[3][3] += wv.w * av.w;
        }
        __syncthreads();
    }
    float g = gamma[0];
    #pragma unroll
    for (int r = 0; r < 4; r++) {
        int c = c0 + cj * 4 + r;
        size_t base = ((size_t)n * C + c) * P + p0 + pi * 4;
        float4 xr = *(const float4*)&x[base];
        float b = bp[c];
        float4 v;
        v.x = g * (acc[r][0] + b) + xr.x;
        v.y = g * (acc[r][1] + b) + xr.y;
        v.z = g * (acc[r][2] + b) + xr.z;
        v.w = g * (acc[r][3] + b) + xr.w;
        *(float4*)&out[base] = v;
    }
}

// ---------------- launch ----------------
extern "C" void kernel_launch(void* const* d_in, const int* in_sizes, int n_in,
                              void* d_out, int out_size) {
    const float* x     = (const float*)d_in[0];
    const float* Wq    = (const float*)d_in[1];
    const float* Wk    = (const float*)d_in[2];
    const float* Wv    = (const float*)d_in[3];
    const float* Wx    = (const float*)d_in[4];
    const float* Wy    = (const float*)d_in[5];
    const float* Wproj = (const float*)d_in[6];
    const float* bproj = (const float*)d_in[7];
    const float* Wc    = (const float*)d_in[8];
    const float* bc    = (const float*)d_in[9];
    const float* gamma = (const float*)d_in[10];
    float* out = (float*)d_out;

    float *wt, *xkv, *qt, *khi, *klo, *vhi, *vlo;
    float *pfx, *pfy, *ctx, *mix, *exb, *eyb, *attn, *aot;
    cudaGetSymbolAddress((void**)&wt,  g_wt);
    cudaGetSymbolAddress((void**)&xkv, g_xkv);
    cudaGetSymbolAddress((void**)&qt,  g_qt);
    cudaGetSymbolAddress((void**)&khi, g_khi);
    cudaGetSymbolAddress((void**)&klo, g_klo);
    cudaGetSymbolAddress((void**)&vhi, g_vhi);
    cudaGetSymbolAddress((void**)&vlo, g_vlo);
    cudaGetSymbolAddress((void**)&pfx, g_pfx);
    cudaGetSymbolAddress((void**)&pfy, g_pfy);
    cudaGetSymbolAddress((void**)&ctx, g_ctx);
    cudaGetSymbolAddress((void**)&mix, g_mix);
    cudaGetSymbolAddress((void**)&exb, g_ex);
    cudaGetSymbolAddress((void**)&eyb, g_ey);
    cudaGetSymbolAddress((void**)&attn, g_attn);
    cudaGetSymbolAddress((void**)&aot, g_aot);

    size_t fa_smem = (size_t)FA2_SMEM * sizeof(float);
    cudaFuncSetAttribute(fused_attn_kernel, cudaFuncAttributeMaxDynamicSharedMemorySize,
                         (int)fa_smem);

    transpose_kernel<<<dim3(9, 9, 4), dim3(32, 8)>>>(Wq, Wk, Wv, Wproj, wt);
    xkv_kernel<<<(NB * C * S + 255) / 256, 256>>>(x, xkv);
    qkvproj_kernel<<<dim3(96, 3, NB), 384>>>(x, xkv, wt, qt, khi, klo, vhi, vlo);
    context_kernel<<<dim3(C / 32, NB), 256>>>(qt, ctx);
    mix_kernel<<<NB, 32>>>(ctx, Wc, bc, mix);
    pos_kernel<<<dim3(WKV, W), 288>>>(Wx, Wy, pfx, pfy);
    ex_kernel<<<dim3(W, M, NB), 256>>>(qt, pfx, exb);
    ey_kernel<<<dim3(H, M, NB), 256>>>(qt, pfy, eyb);
    fused_attn_kernel<<<dim3(P / 32, NB), 512, fa_smem>>>(qt, khi, klo, exb, eyb, mix, attn);
    av_kernel<<<dim3(3, P / 64, NB), 256>>>(attn, vhi, vlo, aot);
    final_kernel<<<dim3(P / 64, 3, NB), 384>>>(aot, wt + 3 * C * C, bproj, x, gamma, out);
}

// round 8
// speedup vs baseline: 1.3145x; 1.0819x over previous
#include <cuda_runtime.h>
#include <cuda_bf16.h>
#include <math.h>
#include <stdint.h>

#define NB   2
#define C    288
#define M    9
#define D    32
#define H    64
#define W    64
#define P    4096
#define HKV  32
#define WKV  32
#define S    1024
#define FEAT 144
#define C2   (C / 2)     // 144
#define S2   (S / 2)     // 512

// ---------------- device scratch ----------------
__device__ float    g_wt [4 * C * C];        // transposed weights
__device__ float    g_xkv[NB * C * S];
__device__ float    g_qt [NB * P * C];       // [n][p][o] fp32
__device__ uint32_t g_khp[NB * S * C2];      // K packed bf16x2 (pairs along d), hi
__device__ uint32_t g_klp[NB * S * C2];      // lo
__device__ uint32_t g_vhp[NB * C * S2];      // V packed bf16x2 (pairs along s), hi
__device__ uint32_t g_vlp[NB * C * S2];
__device__ float    g_pfx[M * W * D * WKV];  // [m][i][d][j]
__device__ float    g_pfy[M * H * D * HKV];
__device__ float    g_ctxp[NB * 16 * C];     // partial context sums
__device__ float    g_mix[NB * M];
__device__ float    g_ex [NB * M * P * 32];  // [n][m][p][v]
__device__ float    g_ey [NB * M * P * 32];  // [n][m][p][u]
__device__ uint32_t g_ahp[(size_t)NB * P * S2];  // attn packed bf16x2 (pairs along s), hi
__device__ uint32_t g_alp[(size_t)NB * P * S2];
__device__ float    g_aot[NB * C * P];       // attn output transposed [n][o][p]

// ---------------- bf16 helpers ----------------
__device__ __forceinline__ float bf16f(float x) {
    return __bfloat162float(__float2bfloat16_rn(x));
}
__device__ __forceinline__ uint32_t bpack(float x, float y) {
    __nv_bfloat162 r = __floats2bfloat162_rn(x, y);   // x in low 16, y in high 16
    return *reinterpret_cast<uint32_t*>(&r);
}
__device__ __forceinline__ void mma_bf16(float* c, const uint32_t* a, const uint32_t* b) {
    asm volatile(
        "mma.sync.aligned.m16n8k16.row.col.f32.bf16.bf16.f32 "
        "{%0,%1,%2,%3}, {%4,%5,%6,%7}, {%8,%9}, {%0,%1,%2,%3};"
        : "+f"(c[0]), "+f"(c[1]), "+f"(c[2]), "+f"(c[3])
        : "r"(a[0]), "r"(a[1]), "r"(a[2]), "r"(a[3]), "r"(b[0]), "r"(b[1]));
}

// ---------------- small kernels ----------------
__global__ void transpose_kernel(const float* __restrict__ Wq, const float* __restrict__ Wk,
                                 const float* __restrict__ Wv, const float* __restrict__ Wp,
                                 float* __restrict__ wt) {
    __shared__ float tile[32][33];
    const float* src = (blockIdx.z == 0) ? Wq : (blockIdx.z == 1) ? Wk
                     : (blockIdx.z == 2) ? Wv : Wp;
    float* dst = wt + (size_t)blockIdx.z * C * C;
    int r0 = blockIdx.y * 32, c0 = blockIdx.x * 32;
    int tx = threadIdx.x, ty = threadIdx.y;
    for (int i = ty; i < 32; i += 8) tile[i][tx] = src[(size_t)(r0 + i) * C + c0 + tx];
    __syncthreads();
    for (int i = ty; i < 32; i += 8) dst[(size_t)(c0 + i) * C + r0 + tx] = tile[tx][i];
}

__global__ void xkv_kernel(const float* __restrict__ x, float* __restrict__ xkv) {
    int idx = blockIdx.x * 256 + threadIdx.x;
    if (idx >= NB * C * S) return;
    int s = idx & (S - 1);
    int c = (idx >> 10) % C;
    int n = idx / (C * S);
    int u = s >> 5, v = s & 31;
    xkv[idx] = x[((size_t)n * C + c) * P + u * 128 + v * 2];
}

// Q + K + V projections, one launch.  grid (96, 3, NB), block 384.
// bx<64: Q -> qt (fp32).  bx in [64,80): K -> khp/klp packed (pairs along d).
// bx in [80,96): V -> vhp/vlp packed (pairs along s).
__global__ __launch_bounds__(384)
void qkvproj_kernel(const float* __restrict__ x, const float* __restrict__ xkv,
                    const float* __restrict__ wt, float* __restrict__ qt,
                    uint32_t* __restrict__ khp, uint32_t* __restrict__ klp,
                    uint32_t* __restrict__ vhp, uint32_t* __restrict__ vlp) {
    __shared__ float Xs[32 * 64];
    __shared__ float Ws[32 * 96];
    int bx = blockIdx.x, n = blockIdx.z;
    int o0 = blockIdx.y * 96;
    const float* Xn;
    const float* WT;
    int Pn, p0, kind;
    if (bx < 64) {
        kind = 0; Xn = x + (size_t)n * C * P; Pn = P; p0 = bx * 64; WT = wt;
    } else {
        kind = 1 + ((bx - 64) >> 4);
        Xn = xkv + (size_t)n * C * S; Pn = S; p0 = ((bx - 64) & 15) * 64;
        WT = wt + (size_t)kind * C * C;
    }
    int t = threadIdx.x;
    int pi = t & 15, oj = t >> 4;
    float acc[4][4] = {};
    for (int c0 = 0; c0 < C; c0 += 32) {
        for (int i = t; i < 2048; i += 384)
            Xs[i] = Xn[(size_t)(c0 + (i >> 6)) * Pn + p0 + (i & 63)];
        for (int i = t; i < 3072; i += 384)
            Ws[i] = WT[(size_t)(c0 + i / 96) * C + o0 + i % 96];
        __syncthreads();
        #pragma unroll
        for (int kk = 0; kk < 32; kk++) {
            float4 xv = *(const float4*)&Xs[kk * 64 + pi * 4];
            float4 wv = *(const float4*)&Ws[kk * 96 + oj * 4];
            acc[0][0] += xv.x * wv.x; acc[0][1] += xv.x * wv.y;
            acc[0][2] += xv.x * wv.z; acc[0][3] += xv.x * wv.w;
            acc[1][0] += xv.y * wv.x; acc[1][1] += xv.y * wv.y;
            acc[1][2] += xv.y * wv.z; acc[1][3] += xv.y * wv.w;
            acc[2][0] += xv.z * wv.x; acc[2][1] += xv.z * wv.y;
            acc[2][2] += xv.z * wv.z; acc[2][3] += xv.z * wv.w;
            acc[3][0] += xv.w * wv.x; acc[3][1] += xv.w * wv.y;
            acc[3][2] += xv.w * wv.z; acc[3][3] += xv.w * wv.w;
        }
        __syncthreads();
    }
    if (kind == 0) {
        float* outn = qt + (size_t)n * P * C;
        #pragma unroll
        for (int r = 0; r < 4; r++) {
            float4 v = make_float4(acc[r][0], acc[r][1], acc[r][2], acc[r][3]);
            *(float4*)&outn[(size_t)(p0 + pi * 4 + r) * C + o0 + oj * 4] = v;
        }
    } else if (kind == 1) {
        // K: pack pairs along o (= head dim).  o0, oj*4 are even.
        uint32_t* hp = khp + (size_t)n * S * C2;
        uint32_t* lp = klp + (size_t)n * S * C2;
        int d2 = (o0 + oj * 4) >> 1;
        #pragma unroll
        for (int r = 0; r < 4; r++) {
            int s = p0 + pi * 4 + r;
            float h0 = bf16f(acc[r][0]), h1 = bf16f(acc[r][1]);
            float h2 = bf16f(acc[r][2]), h3 = bf16f(acc[r][3]);
            hp[(size_t)s * C2 + d2]     = bpack(h0, h1);
            hp[(size_t)s * C2 + d2 + 1] = bpack(h2, h3);
            lp[(size_t)s * C2 + d2]     = bpack(acc[r][0] - h0, acc[r][1] - h1);
            lp[(size_t)s * C2 + d2 + 1] = bpack(acc[r][2] - h2, acc[r][3] - h3);
        }
    } else {
        // V: pack pairs along s.  p0, pi*4 are even.
        uint32_t* hp = vhp + (size_t)n * C * S2;
        uint32_t* lp = vlp + (size_t)n * C * S2;
        int s2 = (p0 + pi * 4) >> 1;
        #pragma unroll
        for (int c = 0; c < 4; c++) {
            int o = o0 + oj * 4 + c;
            float h0 = bf16f(acc[0][c]), h1 = bf16f(acc[1][c]);
            float h2 = bf16f(acc[2][c]), h3 = bf16f(acc[3][c]);
            hp[(size_t)o * S2 + s2]     = bpack(h0, h1);
            hp[(size_t)o * S2 + s2 + 1] = bpack(h2, h3);
            lp[(size_t)o * S2 + s2]     = bpack(acc[0][c] - h0, acc[1][c] - h1);
            lp[(size_t)o * S2 + s2 + 1] = bpack(acc[2][c] - h2, acc[3][c] - h3);
        }
    }
}

// partial context sums: ctxp[n][pc][o] = sum over 256 p's.  grid (9, 16, NB), block 256
__global__ void context_kernel(const float* __restrict__ qt, float* __restrict__ ctxp) {
    int o0 = blockIdx.x * 32, pc = blockIdx.y, n = blockIdx.z;
    int lane = threadIdx.x & 31, w = threadIdx.x >> 5;
    const float* q = qt + ((size_t)n * P + pc * 256) * C + o0 + lane;
    float s = 0.f;
    #pragma unroll
    for (int k = 0; k < 32; k++) s += q[(size_t)(w + 8 * k) * C];
    __shared__ float red[8][32];
    red[w][lane] = s;
    __syncthreads();
    if (w == 0) {
        float tot = 0.f;
        #pragma unroll
        for (int i = 0; i < 8; i++) tot += red[i][lane];
        ctxp[((size_t)n * 16 + pc) * C + o0 + lane] = tot;
    }
}

// reduce partials + logits + softmax.  grid NB, block 288
__global__ void mix_kernel(const float* __restrict__ ctxp, const float* __restrict__ Wc,
                           const float* __restrict__ bc, float* __restrict__ mixw) {
    int n = blockIdx.x, t = threadIdx.x;
    __shared__ float cs[C];
    __shared__ float lg[M];
    float v = 0.f;
    #pragma unroll
    for (int j = 0; j < 16; j++) v += ctxp[((size_t)n * 16 + j) * C + t];
    cs[t] = v * (1.0f / (float)P);
    __syncthreads();
    if (t < M) {
        float s = bc[t];
        const float* wm = Wc + t * C;
        for (int o = 0; o < C; o++) s += cs[o] * wm[o];
        lg[t] = s;
    }
    __syncthreads();
    if (t == 0) {
        float mx = lg[0];
        #pragma unroll
        for (int i = 1; i < M; i++) mx = fmaxf(mx, lg[i]);
        float e[M], sum = 0.f;
        #pragma unroll
        for (int i = 0; i < M; i++) { e[i] = expf(lg[i] - mx); sum += e[i]; }
        #pragma unroll
        for (int i = 0; i < M; i++) mixw[n * M + i] = e[i] / sum;
    }
}

__global__ void pos_kernel(const float* __restrict__ Wx, const float* __restrict__ Wy,
                           float* __restrict__ pfx, float* __restrict__ pfy) {
    __shared__ float emb[FEAT];
    int j = blockIdx.x, i = blockIdx.y;
    int t = threadIdx.x;
    float diff = (float)i - 2.0f * (float)j;
    if (t < FEAT) {
        int l = (t < 72) ? t : (t - 72);
        float dm = powf(1000.0f, (4.0f / 288.0f) * (float)l);
        float wd = diff / dm;
        emb[t] = (t < 72) ? sinf(wd) : cosf(wd);
    }
    __syncthreads();
    float sx = 0.f, sy = 0.f;
    const float* wxr = Wx + t * FEAT;
    const float* wyr = Wy + t * FEAT;
    #pragma unroll 4
    for (int l = 0; l < FEAT; l++) {
        float e = emb[l];
        sx += e * wxr[l];
        sy += e * wyr[l];
    }
    const float inv_sqrt2 = 0.70710678118654752f;
    int m = t >> 5, dd = t & 31;
    int idx = ((m * 64 + i) * 32 + dd) * 32 + j;
    pfx[idx] = sx * inv_sqrt2;
    pfy[idx] = sy * inv_sqrt2;
}

__global__ __launch_bounds__(256)
void ex_kernel(const float* __restrict__ qt, const float* __restrict__ pfx,
               float* __restrict__ ex) {
    __shared__ float qs[64 * 33];
    __shared__ float pfs[32 * 33];
    int w = blockIdx.x, m = blockIdx.y, n = blockIdx.z;
    int t = threadIdx.x;
    for (int i = t; i < 1024; i += 256)
        pfs[(i >> 5) * 33 + (i & 31)] = pfx[(m * 64 + w) * 1024 + i];
    for (int i = t; i < 2048; i += 256) {
        int hh = i >> 5, dd = i & 31;
        qs[hh * 33 + dd] = qt[((size_t)n * P + hh * 64 + w) * C + m * 32 + dd];
    }
    __syncthreads();
    int v = t & 31, h0 = t >> 5;
    #pragma unroll
    for (int r = 0; r < 8; r++) {
        int h = h0 + 8 * r;
        float a = 0.f;
        #pragma unroll
        for (int dd = 0; dd < 32; dd++)
            a += qs[h * 33 + dd] * pfs[dd * 33 + v];
        ex[((size_t)(n * M + m) * P + h * 64 + w) * 32 + v] = a;
    }
}

__global__ __launch_bounds__(256)
void ey_kernel(const float* __restrict__ qt, const float* __restrict__ pfy,
               float* __restrict__ ey) {
    __shared__ float qs[64 * 33];
    __shared__ float pfs[32 * 33];
    int h = blockIdx.x, m = blockIdx.y, n = blockIdx.z;
    int t = threadIdx.x;
    for (int i = t; i < 1024; i += 256)
        pfs[(i >> 5) * 33 + (i & 31)] = pfy[(m * 64 + h) * 1024 + i];
    for (int i = t; i < 2048; i += 256) {
        int ww = i >> 5, dd = i & 31;
        qs[ww * 33 + dd] = qt[((size_t)n * P + h * 64 + ww) * C + m * 32 + dd];
    }
    __syncthreads();
    int u = t & 31, w0 = t >> 5;
    #pragma unroll
    for (int r = 0; r < 8; r++) {
        int ww = w0 + 8 * r;
        float a = 0.f;
        #pragma unroll
        for (int dd = 0; dd < 32; dd++)
            a += qs[ww * 33 + dd] * pfs[dd * 33 + u];
        ey[((size_t)(n * M + m) * P + h * 64 + ww) * 32 + u] = a;
    }
}

// ---------------- fused energy + softmax + head-mix (bf16x3 mma) ----------------
// 512 threads, 32 query rows/block.  Output: attn packed bf16x2 hi/lo.
// smem words: E 32*1025 | EX/EY 1024+1024 | QH/QL 32*20 | KH/KL 256*20
#define FB_E     (32 * 1025)
#define FB_WORDS (FB_E + 2048 + 2 * (32 * 20) + 2 * (256 * 20))

__global__ __launch_bounds__(512, 1)
void fused_attn_kernel(const float* __restrict__ qt, const uint32_t* __restrict__ khp,
                       const uint32_t* __restrict__ klp, const float* __restrict__ ex,
                       const float* __restrict__ ey, const float* __restrict__ mixw,
                       uint32_t* __restrict__ ahp, uint32_t* __restrict__ alp) {
    extern __shared__ float sm[];
    float*    E   = sm;                       // [32][1025]
    float*    EXs = E + FB_E;                 // 1024
    float*    EYs = EXs + 1024;               // 1024
    uint32_t* QH  = (uint32_t*)(EYs + 1024);  // [32][20]
    uint32_t* QL  = QH + 32 * 20;
    uint32_t* KH  = QL + 32 * 20;             // [256][20]
    uint32_t* KL  = KH + 256 * 20;

    int t = threadIdx.x;
    int p0 = blockIdx.x * 32;
    int n = blockIdx.y;
    int warp = t >> 5, lane = t & 31, g = lane >> 2, tg = lane & 3;
    int wp = warp & 1;          // row half (16 rows)
    int ws = warp >> 1;         // 0..7: 32-col segment of 256-col chunk

    const float* qn = qt + (size_t)n * P * C;
    float acc[2][32];
    #pragma unroll
    for (int a = 0; a < 2; a++)
        #pragma unroll
        for (int j = 0; j < 32; j++) acc[a][j] = 0.f;

    for (int m = 0; m < M; m++) {
        // Q tile: load fp32, split+pack (pairs along d). 512 thr x 1 pair = 32x16.
        {
            int pl = t >> 4, d2 = t & 15;
            float2 qv = *(const float2*)&qn[(size_t)(p0 + pl) * C + m * 32 + 2 * d2];
            float xh = bf16f(qv.x), yh = bf16f(qv.y);
            QH[pl * 20 + d2] = bpack(xh, yh);
            QL[pl * 20 + d2] = bpack(qv.x - xh, qv.y - yh);
        }
        size_t exbase = ((size_t)(n * M + m) * P + p0) * 32;
        for (int i = t; i < 1024; i += 512) { EXs[i] = ex[exbase + i]; EYs[i] = ey[exbase + i]; }

        for (int ch = 0; ch < 4; ch++) {
            int s0 = ch * 256;
            // K chunk: 256 rows x 16 uint32 x {hi,lo} via uint4
            for (int i = t; i < 2048; i += 512) {
                int buf = i >> 10, r = (i >> 2) & 255, c4 = i & 3;
                const uint32_t* src = (buf ? klp : khp)
                    + ((size_t)n * S + s0 + r) * C2 + m * 16 + c4 * 4;
                uint32_t* dst = (buf ? KL : KH) + r * 20 + c4 * 4;
                *(uint4*)dst = *(const uint4*)src;
            }
            __syncthreads();
            float eacc[4][4] = {};
            #pragma unroll
            for (int ki = 0; ki < 2; ki++) {
                uint32_t ah[4], al[4];
                int pb = wp * 16;
                ah[0] = QH[(pb + g) * 20 + 8 * ki + tg];
                ah[1] = QH[(pb + g + 8) * 20 + 8 * ki + tg];
                ah[2] = QH[(pb + g) * 20 + 8 * ki + tg + 4];
                ah[3] = QH[(pb + g + 8) * 20 + 8 * ki + tg + 4];
                al[0] = QL[(pb + g) * 20 + 8 * ki + tg];
                al[1] = QL[(pb + g + 8) * 20 + 8 * ki + tg];
                al[2] = QL[(pb + g) * 20 + 8 * ki + tg + 4];
                al[3] = QL[(pb + g + 8) * 20 + 8 * ki + tg + 4];
                #pragma unroll
                for (int nf = 0; nf < 4; nf++) {
                    int sb = ws * 32 + nf * 8;
                    uint32_t bh[2], bl[2];
                    bh[0] = KH[(sb + g) * 20 + 8 * ki + tg];
                    bh[1] = KH[(sb + g) * 20 + 8 * ki + tg + 4];
                    bl[0] = KL[(sb + g) * 20 + 8 * ki + tg];
                    bl[1] = KL[(sb + g) * 20 + 8 * ki + tg + 4];
                    mma_bf16(eacc[nf], ah, bh);
                    mma_bf16(eacc[nf], ah, bl);
                    mma_bf16(eacc[nf], al, bh);
                }
            }
            // epilogue: add pos bias, write E
            #pragma unroll
            for (int nf = 0; nf < 4; nf++) {
                int sgl = s0 + ws * 32 + nf * 8 + tg * 2;
                int u = sgl >> 5, v0 = sgl & 31, v1 = (sgl + 1) & 31;
                #pragma unroll
                for (int half = 0; half < 2; half++) {
                    int pl = wp * 16 + g + half * 8;
                    E[pl * 1025 + sgl]     = eacc[nf][half * 2]
                                             + EXs[pl * 32 + v0] + EYs[pl * 32 + u];
                    E[pl * 1025 + sgl + 1] = eacc[nf][half * 2 + 1]
                                             + EXs[pl * 32 + v1] + EYs[pl * 32 + u];
                }
            }
            __syncthreads();
        }

        // softmax: warp owns rows (warp, warp+16); pure intra-warp
        float wm = mixw[n * M + m];
        #pragma unroll
        for (int rr = 0; rr < 2; rr++) {
            float* Er = E + (warp + rr * 16) * 1025;
            float mx = -1e30f;
            #pragma unroll
            for (int j = 0; j < 32; j++) mx = fmaxf(mx, Er[lane + 32 * j]);
            #pragma unroll
            for (int off = 16; off > 0; off >>= 1)
                mx = fmaxf(mx, __shfl_xor_sync(0xffffffffu, mx, off));
            float ssum = 0.f;
            #pragma unroll
            for (int j = 0; j < 32; j++) {
                float v = __expf(Er[lane + 32 * j] - mx);
                Er[lane + 32 * j] = v;
                ssum += v;
            }
            #pragma unroll
            for (int off = 16; off > 0; off >>= 1)
                ssum += __shfl_xor_sync(0xffffffffu, ssum, off);
            float sc = wm / ssum;
            #pragma unroll
            for (int j = 0; j < 32; j++)
                acc[rr][j] += sc * Er[lane + 32 * j];
        }
    }

    // write acc to E, then pack bf16x2 pairs along s and store
    #pragma unroll
    for (int rr = 0; rr < 2; rr++) {
        float* Er = E + (warp + rr * 16) * 1025;
        #pragma unroll
        for (int j = 0; j < 32; j++)
            Er[lane + 32 * j] = acc[rr][j];
    }
    __syncthreads();
    {
        int row = t >> 4, cb = (t & 15) * 32;
        uint32_t* ho = ahp + (((size_t)n * P + p0 + row) << 9) + cb;
        uint32_t* lo = alp + (((size_t)n * P + p0 + row) << 9) + cb;
        const float* Er = E + row * 1025 + 2 * cb;
        #pragma unroll
        for (int i = 0; i < 32; i++) {
            float a = Er[2 * i], b = Er[2 * i + 1];
            float xh = bf16f(a), yh = bf16f(b);
            ho[i] = bpack(xh, yh);
            lo[i] = bpack(a - xh, b - yh);
        }
    }
}

// ---------------- AV GEMM (bf16x3 mma, all operands pre-packed) ----------------
// grid (3, P/64, NB), block 256 (8 warps: 2p x 4o, warp tile 32p x 24o)
__global__ __launch_bounds__(256)
void av_kernel(const uint32_t* __restrict__ ahp, const uint32_t* __restrict__ alp,
               const uint32_t* __restrict__ vhp, const uint32_t* __restrict__ vlp,
               float* __restrict__ aot) {
    __shared__ uint32_t smbuf[2 * 64 * 36 + 2 * 96 * 36];
    uint32_t* AH = smbuf;                 // [64][36]
    uint32_t* AL = AH + 64 * 36;
    uint32_t* VH = AL + 64 * 36;          // [96][36]
    uint32_t* VL = VH + 96 * 36;

    int o0 = blockIdx.x * 96, p0 = blockIdx.y * 64, n = blockIdx.z;
    int t = threadIdx.x;
    int warp = t >> 5, lane = t & 31;
    int g = lane >> 2, tg = lane & 3;
    int wp = warp & 1, wo = warp >> 1;

    float acc[2][3][4];
    #pragma unroll
    for (int a = 0; a < 2; a++)
        #pragma unroll
        for (int b = 0; b < 3; b++)
            #pragma unroll
            for (int c = 0; c < 4; c++) acc[a][b][c] = 0.f;

    for (int k0 = 0; k0 < S; k0 += 64) {
        int kb = k0 >> 1;   // 32 uint32 per row this chunk
        for (int i = t; i < 1024; i += 256) {           // A: 64 rows x 8 uint4 x 2
            int buf = i >> 9, ii = i & 511, r = ii >> 3, c = ii & 7;
            const uint32_t* src = (buf ? alp : ahp)
                + (((size_t)n * P + p0 + r) << 9) + kb + c * 4;
            *(uint4*)&(buf ? AL : AH)[r * 36 + c * 4] = *(const uint4*)src;
        }
        for (int i = t; i < 1536; i += 256) {           // V: 96 rows x 8 uint4 x 2
            int buf = i >= 768, ii = buf ? i - 768 : i, r = ii >> 3, c = ii & 7;
            const uint32_t* src = (buf ? vlp : vhp)
                + (((size_t)n * C + o0 + r) << 9) + kb + c * 4;
            *(uint4*)&(buf ? VL : VH)[r * 36 + c * 4] = *(const uint4*)src;
        }
        __syncthreads();
        #pragma unroll
        for (int ki = 0; ki < 4; ki++) {
            uint32_t ah[2][4], al[2][4];
            #pragma unroll
            for (int mt = 0; mt < 2; mt++) {
                int pb = wp * 32 + mt * 16;
                ah[mt][0] = AH[(pb + g) * 36 + 8 * ki + tg];
                ah[mt][1] = AH[(pb + g + 8) * 36 + 8 * ki + tg];
                ah[mt][2] = AH[(pb + g) * 36 + 8 * ki + tg + 4];
                ah[mt][3] = AH[(pb + g + 8) * 36 + 8 * ki + tg + 4];
                al[mt][0] = AL[(pb + g) * 36 + 8 * ki + tg];
                al[mt][1] = AL[(pb + g + 8) * 36 + 8 * ki + tg];
                al[mt][2] = AL[(pb + g) * 36 + 8 * ki + tg + 4];
                al[mt][3] = AL[(pb + g + 8) * 36 + 8 * ki + tg + 4];
            }
            #pragma unroll
            for (int nf = 0; nf < 3; nf++) {
                int ob = wo * 24 + nf * 8;
                uint32_t bh[2], bl[2];
                bh[0] = VH[(ob + g) * 36 + 8 * ki + tg];
                bh[1] = VH[(ob + g) * 36 + 8 * ki + tg + 4];
                bl[0] = VL[(ob + g) * 36 + 8 * ki + tg];
                bl[1] = VL[(ob + g) * 36 + 8 * ki + tg + 4];
                #pragma unroll
                for (int mt = 0; mt < 2; mt++) {
                    mma_bf16(acc[mt][nf], ah[mt], bh);
                    mma_bf16(acc[mt][nf], ah[mt], bl);
                    mma_bf16(acc[mt][nf], al[mt], bh);
                }
            }
        }
        __syncthreads();
    }

    // stage transposed [o][p], coalesced store
    float* stage = (float*)smbuf;   // 96*68 floats fits
    #pragma unroll
    for (int mt = 0; mt < 2; mt++)
        #pragma unroll
        for (int nf = 0; nf < 3; nf++)
            #pragma unroll
            for (int c = 0; c < 4; c++) {
                int oo = wo * 24 + nf * 8 + tg * 2 + (c & 1);
                int pp = wp * 32 + mt * 16 + g + ((c >> 1) * 8);
                stage[oo * 68 + pp] = acc[mt][nf][c];
            }
    __syncthreads();
    float* ab = aot + ((size_t)n * C + o0) * P + p0;
    for (int i = t; i < 96 * 64; i += 256) {
        int orr = i >> 6, pc = i & 63;
        ab[(size_t)orr * P + pc] = stage[orr * 68 + pc];
    }
}

// out[n][c][p] = gamma*(sum_o At[n][o][p]*WpT[o][c] + bp[c]) + x[n][c][p]
__global__ __launch_bounds__(384)
void final_kernel(const float* __restrict__ At, const float* __restrict__ WpT,
                  const float* __restrict__ bp, const float* __restrict__ x,
                  const float* __restrict__ gamma, float* __restrict__ out) {
    __shared__ float As[32 * 64];
    __shared__ float Ws[32 * 96];
    int n = blockIdx.z;
    const float* An = At + (size_t)n * C * P;
    int p0 = blockIdx.x * 64, c0 = blockIdx.y * 96;
    int t = threadIdx.x;
    int pi = t & 15, cj = t >> 4;
    float acc[4][4] = {};
    for (int o0 = 0; o0 < C; o0 += 32) {
        for (int i = t; i < 2048; i += 384)
            As[i] = An[(size_t)(o0 + (i >> 6)) * P + p0 + (i & 63)];
        for (int i = t; i < 3072; i += 384)
            Ws[i] = WpT[(size_t)(o0 + i / 96) * C + c0 + i % 96];
        __syncthreads();
        #pragma unroll
        for (int kk = 0; kk < 32; kk++) {
            float4 av = *(const float4*)&As[kk * 64 + pi * 4];
            float4 wv = *(const float4*)&Ws[kk * 96 + cj * 4];
            acc[0][0] += wv.x * av.x; acc[0][1] += wv.x * av.y;
            acc[0][2] += wv.x * av.z; acc[0][3] += wv.x * av.w;
            acc[1][0] += wv.y * av.x; acc[1][1] += wv.y * av.y;
            acc[1][2] += wv.y * av.z; acc[1][3] += wv.y * av.w;
            acc[2][0] += wv.z * av.x; acc[2][1] += wv.z * av.y;
            acc[2][2] += wv.z * av.z; acc[2][3] += wv.z * av.w;
            acc[3][0] += wv.w * av.x; acc[3][1] += wv.w * av.y;
            acc[3][2] += wv.w * av.z; acc[3][3] += wv.w * av.w;
        }
        __syncthreads();
    }
    float g = gamma[0];
    #pragma unroll
    for (int r = 0; r < 4; r++) {
        int c = c0 + cj * 4 + r;
        size_t base = ((size_t)n * C + c) * P + p0 + pi * 4;
        float4 xr = *(const float4*)&x[base];
        float b = bp[c];
        float4 v;
        v.x = g * (acc[r][0] + b) + xr.x;
        v.y = g * (acc[r][1] + b) + xr.y;
        v.z = g * (acc[r][2] + b) + xr.z;
        v.w = g * (acc[r][3] + b) + xr.w;
        *(float4*)&out[base] = v;
    }
}

// ---------------- launch ----------------
extern "C" void kernel_launch(void* const* d_in, const int* in_sizes, int n_in,
                              void* d_out, int out_size) {
    const float* x     = (const float*)d_in[0];
    const float* Wq    = (const float*)d_in[1];
    const float* Wk    = (const float*)d_in[2];
    const float* Wv    = (const float*)d_in[3];
    const float* Wx    = (const float*)d_in[4];
    const float* Wy    = (const float*)d_in[5];
    const float* Wproj = (const float*)d_in[6];
    const float* bproj = (const float*)d_in[7];
    const float* Wc    = (const float*)d_in[8];
    const float* bc    = (const float*)d_in[9];
    const float* gamma = (const float*)d_in[10];
    float* out = (float*)d_out;

    float *wt, *xkv, *qt, *pfx, *pfy, *ctxp, *mix, *exb, *eyb, *aot;
    uint32_t *khp, *klp, *vhp, *vlp, *ahp, *alp;
    cudaGetSymbolAddress((void**)&wt,   g_wt);
    cudaGetSymbolAddress((void**)&xkv,  g_xkv);
    cudaGetSymbolAddress((void**)&qt,   g_qt);
    cudaGetSymbolAddress((void**)&khp,  g_khp);
    cudaGetSymbolAddress((void**)&klp,  g_klp);
    cudaGetSymbolAddress((void**)&vhp,  g_vhp);
    cudaGetSymbolAddress((void**)&vlp,  g_vlp);
    cudaGetSymbolAddress((void**)&pfx,  g_pfx);
    cudaGetSymbolAddress((void**)&pfy,  g_pfy);
    cudaGetSymbolAddress((void**)&ctxp, g_ctxp);
    cudaGetSymbolAddress((void**)&mix,  g_mix);
    cudaGetSymbolAddress((void**)&exb,  g_ex);
    cudaGetSymbolAddress((void**)&eyb,  g_ey);
    cudaGetSymbolAddress((void**)&ahp,  g_ahp);
    cudaGetSymbolAddress((void**)&alp,  g_alp);
    cudaGetSymbolAddress((void**)&aot,  g_aot);

    size_t fa_smem = (size_t)FB_WORDS * sizeof(float);
    cudaFuncSetAttribute(fused_attn_kernel, cudaFuncAttributeMaxDynamicSharedMemorySize,
                         (int)fa_smem);

    transpose_kernel<<<dim3(9, 9, 4), dim3(32, 8)>>>(Wq, Wk, Wv, Wproj, wt);
    xkv_kernel<<<(NB * C * S + 255) / 256, 256>>>(x, xkv);
    qkvproj_kernel<<<dim3(96, 3, NB), 384>>>(x, xkv, wt, qt, khp, klp, vhp, vlp);
    context_kernel<<<dim3(9, 16, NB), 256>>>(qt, ctxp);
    mix_kernel<<<NB, 288>>>(ctxp, Wc, bc, mix);
    pos_kernel<<<dim3(WKV, W), 288>>>(Wx, Wy, pfx, pfy);
    ex_kernel<<<dim3(W, M, NB), 256>>>(qt, pfx, exb);
    ey_kernel<<<dim3(H, M, NB), 256>>>(qt, pfy, eyb);
    fused_attn_kernel<<<dim3(P / 32, NB), 512, fa_smem>>>(qt, khp, klp, exb, eyb, mix,
                                                          ahp, alp);
    av_kernel<<<dim3(3, P / 64, NB), 256>>>(ahp, alp, vhp, vlp, aot);
    final_kernel<<<dim3(P / 64, 3, NB), 384>>>(aot, wt + 3 * C * C, bproj, x, gamma, out);
}

// round 10
// speedup vs baseline: 1.3514x; 1.0281x over previous
#include <cuda_runtime.h>
#include <cuda_bf16.h>
#include <math.h>
#include <stdint.h>

#define NB   2
#define C    288
#define M    9
#define D    32
#define H    64
#define W    64
#define P    4096
#define HKV  32
#define WKV  32
#define S    1024
#define FEAT 144
#define C2   (C / 2)     // 144
#define S2   (S / 2)     // 512

// ---------------- device scratch ----------------
__device__ float    g_xkv[NB * C * S];
__device__ float    g_qt [NB * P * C];       // [n][p][o] fp32
__device__ uint32_t g_khp[NB * S * C2];      // K packed bf16x2 (pairs along d), hi
__device__ uint32_t g_klp[NB * S * C2];      // lo
__device__ uint32_t g_vhp[NB * C * S2];      // V packed bf16x2 (pairs along s), hi
__device__ uint32_t g_vlp[NB * C * S2];
__device__ float    g_pfx[M * W * D * WKV];  // [m][i][d][j]
__device__ float    g_pfy[M * H * D * HKV];
__device__ float    g_ctxp[NB * 64 * C];     // per-Q-block context partial sums
__device__ uint32_t g_ahp[(size_t)NB * P * S2];  // attn packed bf16x2 hi
__device__ uint32_t g_alp[(size_t)NB * P * S2];
__device__ float    g_aot[NB * C * P];       // attn output transposed [n][o][p]

// ---------------- bf16 helpers ----------------
__device__ __forceinline__ float bf16f(float x) {
    return __bfloat162float(__float2bfloat16_rn(x));
}
__device__ __forceinline__ uint32_t bpack(float x, float y) {
    __nv_bfloat162 r = __floats2bfloat162_rn(x, y);
    return *reinterpret_cast<uint32_t*>(&r);
}
__device__ __forceinline__ void mma_bf16(float* c, const uint32_t* a, const uint32_t* b) {
    asm volatile(
        "mma.sync.aligned.m16n8k16.row.col.f32.bf16.bf16.f32 "
        "{%0,%1,%2,%3}, {%4,%5,%6,%7}, {%8,%9}, {%0,%1,%2,%3};"
        : "+f"(c[0]), "+f"(c[1]), "+f"(c[2]), "+f"(c[3])
        : "r"(a[0]), "r"(a[1]), "r"(a[2]), "r"(a[3]), "r"(b[0]), "r"(b[1]));
}

// ---------------- pos features (launch 0) ----------------
__global__ void pos_kernel(const float* __restrict__ Wx, const float* __restrict__ Wy,
                           float* __restrict__ pfx, float* __restrict__ pfy) {
    __shared__ float emb[FEAT];
    int j = blockIdx.x, i = blockIdx.y;
    int t = threadIdx.x;
    float diff = (float)i - 2.0f * (float)j;
    if (t < FEAT) {
        int l = (t < 72) ? t : (t - 72);
        float dm = powf(1000.0f, (4.0f / 288.0f) * (float)l);
        float wd = diff / dm;
        emb[t] = (t < 72) ? sinf(wd) : cosf(wd);
    }
    __syncthreads();
    float sx = 0.f, sy = 0.f;
    const float* wxr = Wx + t * FEAT;
    const float* wyr = Wy + t * FEAT;
    #pragma unroll 4
    for (int l = 0; l < FEAT; l++) {
        float e = emb[l];
        sx += e * wxr[l];
        sy += e * wyr[l];
    }
    const float inv_sqrt2 = 0.70710678118654752f;
    int m = t >> 5, dd = t & 31;
    int idx = ((m * 64 + i) * 32 + dd) * 32 + j;
    pfx[idx] = sx * inv_sqrt2;
    pfy[idx] = sy * inv_sqrt2;
}

// ---------------- x_kv gather (launch 1) ----------------
__global__ void xkv_kernel(const float* __restrict__ x, float* __restrict__ xkv) {
    int idx = blockIdx.x * 256 + threadIdx.x;
    if (idx >= NB * C * S) return;
    int s = idx & (S - 1);
    int c = (idx >> 10) % C;
    int n = idx / (C * S);
    int u = s >> 5, v = s & 31;
    xkv[idx] = x[((size_t)n * C + c) * P + u * 128 + v * 2];
}

// ---------------- Q+K+V projections (launch 2) ----------------
// grid (96, 3, NB), block 384.  Weights read directly (transposed smem fill).
// bx<64: Q -> qt (fp32) + context partials.  [64,80): K -> khp/klp.  [80,96): V -> vhp/vlp.
__global__ __launch_bounds__(384)
void qkvproj_kernel(const float* __restrict__ x, const float* __restrict__ xkv,
                    const float* __restrict__ Wq, const float* __restrict__ Wk,
                    const float* __restrict__ Wv,
                    float* __restrict__ qt,
                    uint32_t* __restrict__ khp, uint32_t* __restrict__ klp,
                    uint32_t* __restrict__ vhp, uint32_t* __restrict__ vlp,
                    float* __restrict__ ctxp) {
    __shared__ float Xs[32 * 64];
    __shared__ float Ws[32 * 100];   // [c_local][o_local] pad 100
    int bx = blockIdx.x, n = blockIdx.z;
    int o0 = blockIdx.y * 96;
    const float* Xn;
    const float* Worig;
    int Pn, p0, kind;
    if (bx < 64) {
        kind = 0; Xn = x + (size_t)n * C * P; Pn = P; p0 = bx * 64; Worig = Wq;
    } else {
        kind = 1 + ((bx - 64) >> 4);
        Xn = xkv + (size_t)n * C * S; Pn = S; p0 = ((bx - 64) & 15) * 64;
        Worig = (kind == 1) ? Wk : Wv;
    }
    int t = threadIdx.x;
    int pi = t & 15, oj = t >> 4;
    float acc[4][4] = {};
    for (int c0 = 0; c0 < C; c0 += 32) {
        for (int i = t; i < 2048; i += 384)
            Xs[i] = Xn[(size_t)(c0 + (i >> 6)) * Pn + p0 + (i & 63)];
        for (int i = t; i < 3072; i += 384) {
            int ol = i >> 5, cl = i & 31;
            Ws[cl * 100 + ol] = Worig[(size_t)(o0 + ol) * C + c0 + cl];
        }
        __syncthreads();
        #pragma unroll
        for (int kk = 0; kk < 32; kk++) {
            float4 xv = *(const float4*)&Xs[kk * 64 + pi * 4];
            float4 wv = *(const float4*)&Ws[kk * 100 + oj * 4];
            acc[0][0] += xv.x * wv.x; acc[0][1] += xv.x * wv.y;
            acc[0][2] += xv.x * wv.z; acc[0][3] += xv.x * wv.w;
            acc[1][0] += xv.y * wv.x; acc[1][1] += xv.y * wv.y;
            acc[1][2] += xv.y * wv.z; acc[1][3] += xv.y * wv.w;
            acc[2][0] += xv.z * wv.x; acc[2][1] += xv.z * wv.y;
            acc[2][2] += xv.z * wv.z; acc[2][3] += xv.z * wv.w;
            acc[3][0] += xv.w * wv.x; acc[3][1] += xv.w * wv.y;
            acc[3][2] += xv.w * wv.z; acc[3][3] += xv.w * wv.w;
        }
        __syncthreads();
    }
    if (kind == 0) {
        float* outn = qt + (size_t)n * P * C;
        #pragma unroll
        for (int r = 0; r < 4; r++) {
            float4 v = make_float4(acc[r][0], acc[r][1], acc[r][2], acc[r][3]);
            *(float4*)&outn[(size_t)(p0 + pi * 4 + r) * C + o0 + oj * 4] = v;
        }
        // context partials (deterministic, per-block)
        #pragma unroll
        for (int c = 0; c < 4; c++)
            Xs[(oj * 4 + c) * 16 + pi] = acc[0][c] + acc[1][c] + acc[2][c] + acc[3][c];
        __syncthreads();
        if (t < 96) {
            float s = 0.f;
            #pragma unroll
            for (int i = 0; i < 16; i++) s += Xs[t * 16 + i];
            ctxp[((size_t)n * 64 + bx) * C + o0 + t] = s;
        }
    } else if (kind == 1) {
        uint32_t* hp = khp + (size_t)n * S * C2;
        uint32_t* lp = klp + (size_t)n * S * C2;
        int d2 = (o0 + oj * 4) >> 1;
        #pragma unroll
        for (int r = 0; r < 4; r++) {
            int s = p0 + pi * 4 + r;
            float h0 = bf16f(acc[r][0]), h1 = bf16f(acc[r][1]);
            float h2 = bf16f(acc[r][2]), h3 = bf16f(acc[r][3]);
            hp[(size_t)s * C2 + d2]     = bpack(h0, h1);
            hp[(size_t)s * C2 + d2 + 1] = bpack(h2, h3);
            lp[(size_t)s * C2 + d2]     = bpack(acc[r][0] - h0, acc[r][1] - h1);
            lp[(size_t)s * C2 + d2 + 1] = bpack(acc[r][2] - h2, acc[r][3] - h3);
        }
    } else {
        uint32_t* hp = vhp + (size_t)n * C * S2;
        uint32_t* lp = vlp + (size_t)n * C * S2;
        int s2 = (p0 + pi * 4) >> 1;
        #pragma unroll
        for (int c = 0; c < 4; c++) {
            int o = o0 + oj * 4 + c;
            float h0 = bf16f(acc[0][c]), h1 = bf16f(acc[1][c]);
            float h2 = bf16f(acc[2][c]), h3 = bf16f(acc[3][c]);
            hp[(size_t)o * S2 + s2]     = bpack(h0, h1);
            hp[(size_t)o * S2 + s2 + 1] = bpack(h2, h3);
            lp[(size_t)o * S2 + s2]     = bpack(acc[0][c] - h0, acc[1][c] - h1);
            lp[(size_t)o * S2 + s2 + 1] = bpack(acc[2][c] - h2, acc[3][c] - h3);
        }
    }
}

// ---------------- fused energy + pos-bias + softmax + head-mix (launch 3) ----------------
// 512 threads, 32 query rows/block.  Computes head-mix weights from context partials,
// per-head pos bias in-kernel, bf16x3 mma energy, warp-per-row softmax,
// mix-weighted accumulate, packed bf16x2 attn output.
#define FB_E     (32 * 1025)
#define FB_WORDS (FB_E + 2048 + 2 * (32 * 20) + 2 * (256 * 20) + 32)

__global__ __launch_bounds__(512, 1)
void fused_attn_kernel(const float* __restrict__ qt, const uint32_t* __restrict__ khp,
                       const uint32_t* __restrict__ klp,
                       const float* __restrict__ pfx, const float* __restrict__ pfy,
                       const float* __restrict__ ctxp, const float* __restrict__ Wc,
                       const float* __restrict__ bc,
                       uint32_t* __restrict__ ahp, uint32_t* __restrict__ alp) {
    extern __shared__ float sm[];
    float*    E    = sm;                       // [32][1025]
    float*    EXs  = E + FB_E;                 // 1024
    float*    EYs  = EXs + 1024;               // 1024
    uint32_t* QH   = (uint32_t*)(EYs + 1024);  // [32][20]
    uint32_t* QL   = QH + 32 * 20;
    uint32_t* KH   = QL + 32 * 20;             // [256][20]
    uint32_t* KL   = KH + 256 * 20;
    float*    MIXs = (float*)(KL + 256 * 20);  // 16
    float*    LG   = MIXs + 16;                // 16

    int t = threadIdx.x;
    int p0 = blockIdx.x * 32;
    int n = blockIdx.y;
    int warp = t >> 5, lane = t & 31, g = lane >> 2, tg = lane & 3;
    int wp = warp & 1;          // row half for mma A-frag
    int ws = warp >> 1;         // 32-col segment of 256-col chunk
    int hq = p0 >> 6, wq0 = p0 & 63;
    const float* qn = qt + (size_t)n * P * C;

    // ---- head-mix weights from context partials ----
    for (int i = t; i < C; i += 512) {
        float s = 0.f;
        for (int b = 0; b < 64; b++) s += ctxp[((size_t)n * 64 + b) * C + i];
        E[i] = s * (1.0f / (float)P);
    }
    __syncthreads();
    if (t < M) {
        float s = bc[t];
        const float* wm = Wc + t * C;
        for (int o = 0; o < C; o++) s += E[o] * wm[o];
        LG[t] = s;
    }
    __syncthreads();
    if (t == 0) {
        float mx = LG[0];
        #pragma unroll
        for (int i = 1; i < M; i++) mx = fmaxf(mx, LG[i]);
        float e[M], sum = 0.f;
        #pragma unroll
        for (int i = 0; i < M; i++) { e[i] = expf(LG[i] - mx); sum += e[i]; }
        #pragma unroll
        for (int i = 0; i < M; i++) MIXs[i] = e[i] / sum;
    }
    __syncthreads();

    float acc[2][32];
    #pragma unroll
    for (int a = 0; a < 2; a++)
        #pragma unroll
        for (int j = 0; j < 32; j++) acc[a][j] = 0.f;

    for (int m = 0; m < M; m++) {
        // Q tile: load fp32, split+pack (pairs along d)
        {
            int pl = t >> 4, d2 = t & 15;
            float2 qv = *(const float2*)&qn[(size_t)(p0 + pl) * C + m * 32 + 2 * d2];
            float xh = bf16f(qv.x), yh = bf16f(qv.y);
            QH[pl * 20 + d2] = bpack(xh, yh);
            QL[pl * 20 + d2] = bpack(qv.x - xh, qv.y - yh);
        }
        // pos bias: warp handles rows warp*2, warp*2+1 (fp32, coalesced pf reads)
        #pragma unroll
        for (int rr = 0; rr < 2; rr++) {
            int qi = warp * 2 + rr;
            const float* qp = qn + (size_t)(p0 + qi) * C + m * 32;
            const float* px = pfx + ((size_t)((m * 64 + wq0 + qi) * 32)) * 32;
            const float* py = pfy + ((size_t)((m * 64 + hq) * 32)) * 32;
            float sx = 0.f, sy = 0.f;
            #pragma unroll
            for (int dd = 0; dd < 32; dd++) {
                float qv = __ldg(qp + dd);
                sx += qv * px[dd * 32 + lane];
                sy += qv * py[dd * 32 + lane];
            }
            EXs[qi * 32 + lane] = sx;
            EYs[qi * 32 + lane] = sy;
        }

        for (int ch = 0; ch < 4; ch++) {
            int s0 = ch * 256;
            for (int i = t; i < 2048; i += 512) {
                int buf = i >> 10, r = (i >> 2) & 255, c4 = i & 3;
                const uint32_t* src = (buf ? klp : khp)
                    + ((size_t)n * S + s0 + r) * C2 + m * 16 + c4 * 4;
                uint32_t* dst = (buf ? KL : KH) + r * 20 + c4 * 4;
                *(uint4*)dst = *(const uint4*)src;
            }
            __syncthreads();
            float eacc[4][4] = {};
            #pragma unroll
            for (int ki = 0; ki < 2; ki++) {
                uint32_t ah[4], al[4];
                int pb = wp * 16;
                ah[0] = QH[(pb + g) * 20 + 8 * ki + tg];
                ah[1] = QH[(pb + g + 8) * 20 + 8 * ki + tg];
                ah[2] = QH[(pb + g) * 20 + 8 * ki + tg + 4];
                ah[3] = QH[(pb + g + 8) * 20 + 8 * ki + tg + 4];
                al[0] = QL[(pb + g) * 20 + 8 * ki + tg];
                al[1] = QL[(pb + g + 8) * 20 + 8 * ki + tg];
                al[2] = QL[(pb + g) * 20 + 8 * ki + tg + 4];
                al[3] = QL[(pb + g + 8) * 20 + 8 * ki + tg + 4];
                #pragma unroll
                for (int nf = 0; nf < 4; nf++) {
                    int sb = ws * 32 + nf * 8;
                    uint32_t bh[2], bl[2];
                    bh[0] = KH[(sb + g) * 20 + 8 * ki + tg];
                    bh[1] = KH[(sb + g) * 20 + 8 * ki + tg + 4];
                    bl[0] = KL[(sb + g) * 20 + 8 * ki + tg];
                    bl[1] = KL[(sb + g) * 20 + 8 * ki + tg + 4];
                    mma_bf16(eacc[nf], ah, bh);
                    mma_bf16(eacc[nf], ah, bl);
                    mma_bf16(eacc[nf], al, bh);
                }
            }
            #pragma unroll
            for (int nf = 0; nf < 4; nf++) {
                int sgl = s0 + ws * 32 + nf * 8 + tg * 2;
                int u = sgl >> 5, v0 = sgl & 31, v1 = (sgl + 1) & 31;
                #pragma unroll
                for (int half = 0; half < 2; half++) {
                    int pl = wp * 16 + g + half * 8;
                    E[pl * 1025 + sgl]     = eacc[nf][half * 2]
                                             + EXs[pl * 32 + v0] + EYs[pl * 32 + u];
                    E[pl * 1025 + sgl + 1] = eacc[nf][half * 2 + 1]
                                             + EXs[pl * 32 + v1] + EYs[pl * 32 + u];
                }
            }
            __syncthreads();
        }

        // softmax: warp owns rows (warp, warp+16)
        float wm = MIXs[m];
        #pragma unroll
        for (int rr = 0; rr < 2; rr++) {
            float* Er = E + (warp + rr * 16) * 1025;
            float mx = -1e30f;
            #pragma unroll
            for (int j = 0; j < 32; j++) mx = fmaxf(mx, Er[lane + 32 * j]);
            #pragma unroll
            for (int off = 16; off > 0; off >>= 1)
                mx = fmaxf(mx, __shfl_xor_sync(0xffffffffu, mx, off));
            float ssum = 0.f;
            #pragma unroll
            for (int j = 0; j < 32; j++) {
                float v = __expf(Er[lane + 32 * j] - mx);
                Er[lane + 32 * j] = v;
                ssum += v;
            }
            #pragma unroll
            for (int off = 16; off > 0; off >>= 1)
                ssum += __shfl_xor_sync(0xffffffffu, ssum, off);
            float sc = wm / ssum;
            #pragma unroll
            for (int j = 0; j < 32; j++)
                acc[rr][j] += sc * Er[lane + 32 * j];
        }
    }

    // write acc back to E, then coalesced pack+store
    #pragma unroll
    for (int rr = 0; rr < 2; rr++) {
        float* Er = E + (warp + rr * 16) * 1025;
        #pragma unroll
        for (int j = 0; j < 32; j++)
            Er[lane + 32 * j] = acc[rr][j];
    }
    __syncthreads();
    for (int idx = t; idx < 32 * 512; idx += 512) {
        int row = idx >> 9, col = idx & 511;
        const float* Er = E + row * 1025 + 2 * col;
        float a = Er[0], b = Er[1];
        float xh = bf16f(a), yh = bf16f(b);
        size_t base = ((size_t)n * P + p0 + row) << 9;
        ahp[base + col] = bpack(xh, yh);
        alp[base + col] = bpack(a - xh, b - yh);
    }
}

// ---------------- AV GEMM (launch 4) ----------------
__global__ __launch_bounds__(256)
void av_kernel(const uint32_t* __restrict__ ahp, const uint32_t* __restrict__ alp,
               const uint32_t* __restrict__ vhp, const uint32_t* __restrict__ vlp,
               float* __restrict__ aot) {
    __shared__ uint32_t smbuf[2 * 64 * 36 + 2 * 96 * 36];
    uint32_t* AH = smbuf;
    uint32_t* AL = AH + 64 * 36;
    uint32_t* VH = AL + 64 * 36;
    uint32_t* VL = VH + 96 * 36;

    int o0 = blockIdx.x * 96, p0 = blockIdx.y * 64, n = blockIdx.z;
    int t = threadIdx.x;
    int warp = t >> 5, lane = t & 31;
    int g = lane >> 2, tg = lane & 3;
    int wp = warp & 1, wo = warp >> 1;

    float acc[2][3][4];
    #pragma unroll
    for (int a = 0; a < 2; a++)
        #pragma unroll
        for (int b = 0; b < 3; b++)
            #pragma unroll
            for (int c = 0; c < 4; c++) acc[a][b][c] = 0.f;

    for (int k0 = 0; k0 < S; k0 += 64) {
        int kb = k0 >> 1;
        for (int i = t; i < 1024; i += 256) {
            int buf = i >> 9, ii = i & 511, r = ii >> 3, c = ii & 7;
            const uint32_t* src = (buf ? alp : ahp)
                + (((size_t)n * P + p0 + r) << 9) + kb + c * 4;
            *(uint4*)&(buf ? AL : AH)[r * 36 + c * 4] = *(const uint4*)src;
        }
        for (int i = t; i < 1536; i += 256) {
            int buf = i >= 768, ii = buf ? i - 768 : i, r = ii >> 3, c = ii & 7;
            const uint32_t* src = (buf ? vlp : vhp)
                + (((size_t)n * C + o0 + r) << 9) + kb + c * 4;
            *(uint4*)&(buf ? VL : VH)[r * 36 + c * 4] = *(const uint4*)src;
        }
        __syncthreads();
        #pragma unroll
        for (int ki = 0; ki < 4; ki++) {
            uint32_t ah[2][4], al[2][4];
            #pragma unroll
            for (int mt = 0; mt < 2; mt++) {
                int pb = wp * 32 + mt * 16;
                ah[mt][0] = AH[(pb + g) * 36 + 8 * ki + tg];
                ah[mt][1] = AH[(pb + g + 8) * 36 + 8 * ki + tg];
                ah[mt][2] = AH[(pb + g) * 36 + 8 * ki + tg + 4];
                ah[mt][3] = AH[(pb + g + 8) * 36 + 8 * ki + tg + 4];
                al[mt][0] = AL[(pb + g) * 36 + 8 * ki + tg];
                al[mt][1] = AL[(pb + g + 8) * 36 + 8 * ki + tg];
                al[mt][2] = AL[(pb + g) * 36 + 8 * ki + tg + 4];
                al[mt][3] = AL[(pb + g + 8) * 36 + 8 * ki + tg + 4];
            }
            #pragma unroll
            for (int nf = 0; nf < 3; nf++) {
                int ob = wo * 24 + nf * 8;
                uint32_t bh[2], bl[2];
                bh[0] = VH[(ob + g) * 36 + 8 * ki + tg];
                bh[1] = VH[(ob + g) * 36 + 8 * ki + tg + 4];
                bl[0] = VL[(ob + g) * 36 + 8 * ki + tg];
                bl[1] = VL[(ob + g) * 36 + 8 * ki + tg + 4];
                #pragma unroll
                for (int mt = 0; mt < 2; mt++) {
                    mma_bf16(acc[mt][nf], ah[mt], bh);
                    mma_bf16(acc[mt][nf], ah[mt], bl);
                    mma_bf16(acc[mt][nf], al[mt], bh);
                }
            }
        }
        __syncthreads();
    }

    float* stage = (float*)smbuf;
    #pragma unroll
    for (int mt = 0; mt < 2; mt++)
        #pragma unroll
        for (int nf = 0; nf < 3; nf++)
            #pragma unroll
            for (int c = 0; c < 4; c++) {
                int oo = wo * 24 + nf * 8 + tg * 2 + (c & 1);
                int pp = wp * 32 + mt * 16 + g + ((c >> 1) * 8);
                stage[oo * 68 + pp] = acc[mt][nf][c];
            }
    __syncthreads();
    float* ab = aot + ((size_t)n * C + o0) * P + p0;
    for (int i = t; i < 96 * 64; i += 256) {
        int orr = i >> 6, pc = i & 63;
        ab[(size_t)orr * P + pc] = stage[orr * 68 + pc];
    }
}

// ---------------- output projection + residual (launch 5) ----------------
__global__ __launch_bounds__(384)
void final_kernel(const float* __restrict__ At, const float* __restrict__ Wproj,
                  const float* __restrict__ bp, const float* __restrict__ x,
                  const float* __restrict__ gamma, float* __restrict__ out) {
    __shared__ float As[32 * 64];
    __shared__ float Ws[32 * 100];   // [o_local][c_local] pad 100
    int n = blockIdx.z;
    const float* An = At + (size_t)n * C * P;
    int p0 = blockIdx.x * 64, c0 = blockIdx.y * 96;
    int t = threadIdx.x;
    int pi = t & 15, cj = t >> 4;
    float acc[4][4] = {};
    for (int o0 = 0; o0 < C; o0 += 32) {
        for (int i = t; i < 2048; i += 384)
            As[i] = An[(size_t)(o0 + (i >> 6)) * P + p0 + (i & 63)];
        for (int i = t; i < 3072; i += 384) {
            int cl = i >> 5, ol = i & 31;
            Ws[ol * 100 + cl] = Wproj[(size_t)(c0 + cl) * C + o0 + ol];
        }
        __syncthreads();
        #pragma unroll
        for (int kk = 0; kk < 32; kk++) {
            float4 av = *(const float4*)&As[kk * 64 + pi * 4];
            float4 wv = *(const float4*)&Ws[kk * 100 + cj * 4];
            acc[0][0] += wv.x * av.x; acc[0][1] += wv.x * av.y;
            acc[0][2] += wv.x * av.z; acc[0][3] += wv.x * av.w;
            acc[1][0] += wv.y * av.x; acc[1][1] += wv.y * av.y;
            acc[1][2] += wv.y * av.z; acc[1][3] += wv.y * av.w;
            acc[2][0] += wv.z * av.x; acc[2][1] += wv.z * av.y;
            acc[2][2] += wv.z * av.z; acc[2][3] += wv.z * av.w;
            acc[3][0] += wv.w * av.x; acc[3][1] += wv.w * av.y;
            acc[3][2] += wv.w * av.z; acc[3][3] += wv.w * av.w;
        }
        __syncthreads();
    }
    float g = gamma[0];
    #pragma unroll
    for (int r = 0; r < 4; r++) {
        int c = c0 + cj * 4 + r;
        size_t base = ((size_t)n * C + c) * P + p0 + pi * 4;
        float4 xr = *(const float4*)&x[base];
        float b = bp[c];
        float4 v;
        v.x = g * (acc[r][0] + b) + xr.x;
        v.y = g * (acc[r][1] + b) + xr.y;
        v.z = g * (acc[r][2] + b) + xr.z;
        v.w = g * (acc[r][3] + b) + xr.w;
        *(float4*)&out[base] = v;
    }
}

// ---------------- launch ----------------
extern "C" void kernel_launch(void* const* d_in, const int* in_sizes, int n_in,
                              void* d_out, int out_size) {
    const float* x     = (const float*)d_in[0];
    const float* Wq    = (const float*)d_in[1];
    const float* Wk    = (const float*)d_in[2];
    const float* Wv    = (const float*)d_in[3];
    const float* Wx    = (const float*)d_in[4];
    const float* Wy    = (const float*)d_in[5];
    const float* Wproj = (const float*)d_in[6];
    const float* bproj = (const float*)d_in[7];
    const float* Wc    = (const float*)d_in[8];
    const float* bc    = (const float*)d_in[9];
    const float* gamma = (const float*)d_in[10];
    float* out = (float*)d_out;

    float *xkv, *qt, *pfx, *pfy, *ctxp, *aot;
    uint32_t *khp, *klp, *vhp, *vlp, *ahp, *alp;
    cudaGetSymbolAddress((void**)&xkv,  g_xkv);
    cudaGetSymbolAddress((void**)&qt,   g_qt);
    cudaGetSymbolAddress((void**)&khp,  g_khp);
    cudaGetSymbolAddress((void**)&klp,  g_klp);
    cudaGetSymbolAddress((void**)&vhp,  g_vhp);
    cudaGetSymbolAddress((void**)&vlp,  g_vlp);
    cudaGetSymbolAddress((void**)&pfx,  g_pfx);
    cudaGetSymbolAddress((void**)&pfy,  g_pfy);
    cudaGetSymbolAddress((void**)&ctxp, g_ctxp);
    cudaGetSymbolAddress((void**)&ahp,  g_ahp);
    cudaGetSymbolAddress((void**)&alp,  g_alp);
    cudaGetSymbolAddress((void**)&aot,  g_aot);

    size_t fa_smem = (size_t)FB_WORDS * sizeof(float);
    cudaFuncSetAttribute(fused_attn_kernel, cudaFuncAttributeMaxDynamicSharedMemorySize,
                         (int)fa_smem);

    pos_kernel<<<dim3(WKV, W), 288>>>(Wx, Wy, pfx, pfy);                       // 0
    xkv_kernel<<<(NB * C * S + 255) / 256, 256>>>(x, xkv);                     // 1
    qkvproj_kernel<<<dim3(96, 3, NB), 384>>>(x, xkv, Wq, Wk, Wv, qt,
                                             khp, klp, vhp, vlp, ctxp);        // 2
    fused_attn_kernel<<<dim3(P / 32, NB), 512, fa_smem>>>(qt, khp, klp, pfx, pfy,
                                                          ctxp, Wc, bc, ahp, alp);  // 3
    av_kernel<<<dim3(3, P / 64, NB), 256>>>(ahp, alp, vhp, vlp, aot);          // 4
    final_kernel<<<dim3(P / 64, 3, NB), 384>>>(aot, Wproj, bproj, x, gamma, out);   // 5
}